// round 2
// baseline (speedup 1.0000x reference)
#include <cuda_runtime.h>
#include <math.h>

#define N_NODES 30000
#define N_EDGES 480000
#define IN_F    128
#define NHEAD   4
#define HD      512
#define OUTF    128
#define NEG_SLOPE 0.2f
#define BN_EPS  1e-5f
#define BN_BLOCKS 256
#define SCAN_NB 118   // ceil(30000/256)

// ---------------- scratch ----------------
__device__ float g_h[N_NODES * HD];
__device__ float g_rst[N_NODES * HD];
__device__ float g_el[N_NODES * NHEAD];
__device__ float g_er[N_NODES * NHEAD];
__device__ float g_P[8 * 128];             // [j][k]: j<4 el-head j, j>=4 er-head j-4
__device__ int   g_deg[N_NODES];
__device__ int   g_cursor[N_NODES];
__device__ int   g_ptr[N_NODES + 1];
__device__ int   g_srcs[N_EDGES];
__device__ int   g_blocksum[SCAN_NB];
__device__ int   g_blockoff[SCAN_NB];
__device__ float g_psum[BN_BLOCKS * HD];
__device__ float g_psq[BN_BLOCKS * HD];
__device__ float g_scale[HD];
__device__ float g_shift[HD];

// ---------------- f32x2 helpers ----------------
__device__ __forceinline__ unsigned long long pack2(float x) {
    unsigned long long r;
    asm("mov.b64 %0, {%1, %1};" : "=l"(r) : "f"(x));
    return r;
}
__device__ __forceinline__ void fma2(unsigned long long& d, unsigned long long a,
                                     unsigned long long b) {
    asm("fma.rn.f32x2 %0, %1, %2, %3;" : "=l"(d) : "l"(a), "l"(b), "l"(d));
}
__device__ __forceinline__ float2 unpack2(unsigned long long v) {
    float lo, hi;
    asm("mov.b64 {%0, %1}, %2;" : "=f"(lo), "=f"(hi) : "l"(v));
    return make_float2(lo, hi);
}

// ---------------- zero degree ----------------
__global__ void zero_deg_kernel() {
    int i = blockIdx.x * blockDim.x + threadIdx.x;
    if (i < N_NODES) g_deg[i] = 0;
}

// ---------------- P vectors: P[j] = W_fc[:, head block] @ attn ----------------
__global__ void pvec_kernel(const float* __restrict__ Wfc,
                            const float* __restrict__ attn_l,
                            const float* __restrict__ attn_r) {
    int j = blockIdx.x;          // 0..7
    int k = threadIdx.x;         // 0..127
    int h = j & 3;
    const float* av = ((j < 4) ? attn_l : attn_r) + h * 128;
    const float* wr = Wfc + k * HD + h * 128;
    float s = 0.f;
#pragma unroll
    for (int d4 = 0; d4 < 32; d4++) {
        float4 w = *(const float4*)(wr + d4 * 4);
        float4 a = *(const float4*)(av + d4 * 4);
        s += w.x * a.x + w.y * a.y + w.z * a.z + w.w * a.w;
    }
    g_P[j * 128 + k] = s;
}

// ---------------- el/er = feat @ P ----------------
__global__ __launch_bounds__(256) void elr_kernel(const float* __restrict__ feat) {
    __shared__ float Ps[8][128];
    int t = threadIdx.x;
    for (int i = t; i < 1024; i += 256) Ps[i >> 7][i & 127] = g_P[i];
    __syncthreads();
    int n = blockIdx.x * 8 + (t >> 5);
    int lane = t & 31;
    if (n >= N_NODES) return;
    float4 f = *(const float4*)(feat + n * 128 + lane * 4);
    float s[8];
#pragma unroll
    for (int j = 0; j < 8; j++) {
        const float* p = &Ps[j][lane * 4];
        s[j] = f.x * p[0] + f.y * p[1] + f.z * p[2] + f.w * p[3];
    }
#pragma unroll
    for (int o = 16; o; o >>= 1)
#pragma unroll
        for (int j = 0; j < 8; j++) s[j] += __shfl_xor_sync(0xffffffffu, s[j], o);
    if (lane < 4) {
        g_el[n * 4 + lane] = s[lane];
        g_er[n * 4 + lane] = s[lane + 4];
    }
}

// ---------------- GEMM1: g_h = feat@W_fc ; g_rst = feat@W_res + bias ----------
__global__ __launch_bounds__(256, 2) void gemm1_kernel(
    const float* __restrict__ feat, const float* __restrict__ Wfc,
    const float* __restrict__ Wres, const float* __restrict__ bias) {
    __shared__ unsigned long long As2[32][128];   // packed broadcast pairs
    __shared__ float Bs[32][128];
    const int tid = threadIdx.x;
    const int tx = tid & 15, ty = tid >> 4;
    const int row0 = blockIdx.y * 128;
    const int bx = blockIdx.x;
    const float* B = (bx < 4) ? (Wfc + bx * 128) : (Wres + (bx - 4) * 128);

    unsigned long long acc[8][4];
#pragma unroll
    for (int i = 0; i < 8; i++)
#pragma unroll
        for (int p = 0; p < 4; p++) acc[i][p] = 0ULL;

    for (int kt = 0; kt < 128; kt += 32) {
#pragma unroll
        for (int l = 0; l < 4; l++) {
            int e = (tid + l * 256) * 4;
            int r = e >> 5, k = e & 31;
            float4 v = make_float4(0.f, 0.f, 0.f, 0.f);
            int gr = row0 + r;
            if (gr < N_NODES) v = *(const float4*)(feat + gr * 128 + kt + k);
            As2[k + 0][r] = pack2(v.x); As2[k + 1][r] = pack2(v.y);
            As2[k + 2][r] = pack2(v.z); As2[k + 3][r] = pack2(v.w);
        }
#pragma unroll
        for (int l = 0; l < 4; l++) {
            int e = (tid + l * 256) * 4;
            int k = e >> 7, c = e & 127;
            *(float4*)&Bs[k][c] = *(const float4*)(B + (kt + k) * HD + c);
        }
        __syncthreads();
#pragma unroll
        for (int kk = 0; kk < 32; kk++) {
            unsigned long long a2[8], b2[4];
#pragma unroll
            for (int i = 0; i < 8; i++) a2[i] = As2[kk][ty * 8 + i];
            ulonglong2 t0 = *(const ulonglong2*)&Bs[kk][tx * 8];
            ulonglong2 t1 = *(const ulonglong2*)&Bs[kk][tx * 8 + 4];
            b2[0] = t0.x; b2[1] = t0.y; b2[2] = t1.x; b2[3] = t1.y;
#pragma unroll
            for (int i = 0; i < 8; i++)
#pragma unroll
                for (int p = 0; p < 4; p++) fma2(acc[i][p], a2[i], b2[p]);
        }
        __syncthreads();
    }
#pragma unroll
    for (int i = 0; i < 8; i++) {
        int gr = row0 + ty * 8 + i;
        if (gr >= N_NODES) continue;
#pragma unroll
        for (int p = 0; p < 4; p++) {
            float2 v = unpack2(acc[i][p]);
            int gc = bx * 128 + tx * 8 + p * 2;
            if (gc < 512) {
                g_h[gr * HD + gc] = v.x;
                g_h[gr * HD + gc + 1] = v.y;
            } else {
                int c = gc - 512;
                g_rst[gr * HD + c] = v.x + bias[c];
                g_rst[gr * HD + c + 1] = v.y + bias[c + 1];
            }
        }
    }
}

// ---------------- degree histogram ----------------
__global__ void hist_kernel(const int* __restrict__ dst) {
    int e = blockIdx.x * blockDim.x + threadIdx.x;
    if (e < N_EDGES) atomicAdd(&g_deg[dst[e]], 1);
}

// ---------------- 3-phase scan ----------------
__global__ void scan1_kernel() {
    __shared__ int wsum[8];
    int t = threadIdx.x, b = blockIdx.x;
    int idx = b * 256 + t;
    int lane = t & 31, wid = t >> 5;
    int v = (idx < N_NODES) ? g_deg[idx] : 0;
    int x = v;
#pragma unroll
    for (int o = 1; o < 32; o <<= 1) {
        int y = __shfl_up_sync(0xffffffffu, x, o);
        if (lane >= o) x += y;
    }
    if (lane == 31) wsum[wid] = x;
    __syncthreads();
    if (t == 0) {
        int run = 0;
#pragma unroll
        for (int i = 0; i < 8; i++) { int tmp = wsum[i]; wsum[i] = run; run += tmp; }
        g_blocksum[b] = run;
    }
    __syncthreads();
    int incl = x + wsum[wid];
    if (idx < N_NODES) g_ptr[idx + 1] = incl;   // block-local inclusive
}

__global__ void scan2_kernel() {
    int run = 0;
    for (int i = 0; i < SCAN_NB; i++) {
        int tmp = g_blocksum[i];
        g_blockoff[i] = run;
        run += tmp;
    }
}

__global__ void scan3_kernel() {
    int t = threadIdx.x, b = blockIdx.x;
    int idx = b * 256 + t;
    if (idx >= N_NODES) return;
    int off = g_blockoff[b];
    int incl = g_ptr[idx + 1] + off;
    g_ptr[idx + 1] = incl;
    g_cursor[idx] = incl - g_deg[idx];
    if (idx == 0) g_ptr[0] = 0;
}

// ---------------- scatter edges into CSR ----------------
__global__ void scatter_kernel(const int* __restrict__ src,
                               const int* __restrict__ dst) {
    int e = blockIdx.x * blockDim.x + threadIdx.x;
    if (e < N_EDGES) {
        int p = atomicAdd(&g_cursor[dst[e]], 1);
        g_srcs[p] = src[e];
    }
}

// ---------------- softmax + aggregate: one warp per node, 4 heads ------------
__global__ __launch_bounds__(256) void agg_kernel() {
    int v = blockIdx.x * 8 + (threadIdx.x >> 5);
    int lane = threadIdx.x & 31;
    if (v >= N_NODES) return;
    int start = g_ptr[v], end = g_ptr[v + 1];
    if (start == end) return;   // keep residual+bias only
    float4 er = *(const float4*)(g_er + v * 4);

    float4 a0 = make_float4(0.f, 0.f, 0.f, 0.f);
    float4 a1 = a0, a2 = a0, a3 = a0;
    float d0 = 0.f, d1 = 0.f, d2 = 0.f, d3 = 0.f;

    for (int j = start; j < end; j++) {
        int s = g_srcs[j];
        float4 el = *(const float4*)(g_el + s * 4);            // broadcast
        const float* hp = g_h + s * HD + lane * 4;
        float4 h0 = *(const float4*)(hp);
        float4 h1 = *(const float4*)(hp + 128);
        float4 h2 = *(const float4*)(hp + 256);
        float4 h3 = *(const float4*)(hp + 384);
        float e0 = el.x + er.x; e0 = (e0 > 0.f) ? e0 : NEG_SLOPE * e0;
        float e1 = el.y + er.y; e1 = (e1 > 0.f) ? e1 : NEG_SLOPE * e1;
        float e2 = el.z + er.z; e2 = (e2 > 0.f) ? e2 : NEG_SLOPE * e2;
        float e3 = el.w + er.w; e3 = (e3 > 0.f) ? e3 : NEG_SLOPE * e3;
        float w0 = __expf(e0), w1 = __expf(e1), w2 = __expf(e2), w3 = __expf(e3);
        d0 += w0; d1 += w1; d2 += w2; d3 += w3;
        a0.x += w0 * h0.x; a0.y += w0 * h0.y; a0.z += w0 * h0.z; a0.w += w0 * h0.w;
        a1.x += w1 * h1.x; a1.y += w1 * h1.y; a1.z += w1 * h1.z; a1.w += w1 * h1.w;
        a2.x += w2 * h2.x; a2.y += w2 * h2.y; a2.z += w2 * h2.z; a2.w += w2 * h2.w;
        a3.x += w3 * h3.x; a3.y += w3 * h3.y; a3.z += w3 * h3.z; a3.w += w3 * h3.w;
    }
    float i0 = 1.f / d0, i1 = 1.f / d1, i2 = 1.f / d2, i3 = 1.f / d3;
    float* o = g_rst + v * HD + lane * 4;
    float4 c0 = *(float4*)(o);
    float4 c1 = *(float4*)(o + 128);
    float4 c2 = *(float4*)(o + 256);
    float4 c3 = *(float4*)(o + 384);
    c0.x += a0.x * i0; c0.y += a0.y * i0; c0.z += a0.z * i0; c0.w += a0.w * i0;
    c1.x += a1.x * i1; c1.y += a1.y * i1; c1.z += a1.z * i1; c1.w += a1.w * i1;
    c2.x += a2.x * i2; c2.y += a2.y * i2; c2.z += a2.z * i2; c2.w += a2.w * i2;
    c3.x += a3.x * i3; c3.y += a3.y * i3; c3.z += a3.z * i3; c3.w += a3.w * i3;
    *(float4*)(o)       = c0;
    *(float4*)(o + 128) = c1;
    *(float4*)(o + 256) = c2;
    *(float4*)(o + 384) = c3;
}

// ---------------- BN partials ----------------
__global__ void bn_part_kernel() {
    int c = threadIdx.x;
    float s = 0.f, q = 0.f;
    for (int r = blockIdx.x; r < N_NODES; r += gridDim.x) {
        float x = g_rst[r * HD + c];
        s += x;
        q += x * x;
    }
    g_psum[blockIdx.x * HD + c] = s;
    g_psq[blockIdx.x * HD + c] = q;
}

__global__ void bn_final_kernel(const float* __restrict__ gamma,
                                const float* __restrict__ beta) {
    int c = threadIdx.x;
    float s = 0.f, q = 0.f;
    for (int b = 0; b < BN_BLOCKS; b++) {
        s += g_psum[b * HD + c];
        q += g_psq[b * HD + c];
    }
    float mu = s / (float)N_NODES;
    float var = q / (float)N_NODES - mu * mu;
    float rstd = rsqrtf(var + BN_EPS);
    float sc = gamma[c] * rstd;
    g_scale[c] = sc;
    g_shift[c] = beta[c] - mu * sc;
}

// ---------------- GEMM2: out = ReLU(BN(rst)) @ W_out + b_out -----------------
__global__ __launch_bounds__(256, 2) void gemm2_kernel(
    const float* __restrict__ Wout, const float* __restrict__ bout,
    float* __restrict__ out) {
    __shared__ unsigned long long As2[32][128];
    __shared__ float Bs[32][128];
    const int tid = threadIdx.x;
    const int tx = tid & 15, ty = tid >> 4;
    const int row0 = blockIdx.x * 128;

    unsigned long long acc[8][4];
#pragma unroll
    for (int i = 0; i < 8; i++)
#pragma unroll
        for (int p = 0; p < 4; p++) acc[i][p] = 0ULL;

    for (int kt = 0; kt < 512; kt += 32) {
#pragma unroll
        for (int l = 0; l < 4; l++) {
            int e = (tid + l * 256) * 4;
            int r = e >> 5, k = e & 31;
            float4 val = make_float4(0.f, 0.f, 0.f, 0.f);
            int gr = row0 + r;
            if (gr < N_NODES) {
                float4 x = *(const float4*)(g_rst + gr * HD + kt + k);
                float4 sc = *(const float4*)(g_scale + kt + k);
                float4 sh = *(const float4*)(g_shift + kt + k);
                val.x = fmaxf(sc.x * x.x + sh.x, 0.f);
                val.y = fmaxf(sc.y * x.y + sh.y, 0.f);
                val.z = fmaxf(sc.z * x.z + sh.z, 0.f);
                val.w = fmaxf(sc.w * x.w + sh.w, 0.f);
            }
            As2[k + 0][r] = pack2(val.x); As2[k + 1][r] = pack2(val.y);
            As2[k + 2][r] = pack2(val.z); As2[k + 3][r] = pack2(val.w);
        }
#pragma unroll
        for (int l = 0; l < 4; l++) {
            int e = (tid + l * 256) * 4;
            int k = e >> 7, c = e & 127;
            *(float4*)&Bs[k][c] = *(const float4*)(Wout + (kt + k) * OUTF + c);
        }
        __syncthreads();
#pragma unroll
        for (int kk = 0; kk < 32; kk++) {
            unsigned long long a2[8], b2[4];
#pragma unroll
            for (int i = 0; i < 8; i++) a2[i] = As2[kk][ty * 8 + i];
            ulonglong2 t0 = *(const ulonglong2*)&Bs[kk][tx * 8];
            ulonglong2 t1 = *(const ulonglong2*)&Bs[kk][tx * 8 + 4];
            b2[0] = t0.x; b2[1] = t0.y; b2[2] = t1.x; b2[3] = t1.y;
#pragma unroll
            for (int i = 0; i < 8; i++)
#pragma unroll
                for (int p = 0; p < 4; p++) fma2(acc[i][p], a2[i], b2[p]);
        }
        __syncthreads();
    }
#pragma unroll
    for (int i = 0; i < 8; i++) {
        int gr = row0 + ty * 8 + i;
        if (gr >= N_NODES) continue;
#pragma unroll
        for (int p = 0; p < 4; p++) {
            float2 v = unpack2(acc[i][p]);
            int gc = tx * 8 + p * 2;
            out[gr * OUTF + gc] = v.x + bout[gc];
            out[gr * OUTF + gc + 1] = v.y + bout[gc + 1];
        }
    }
}

// ---------------- launch ----------------
extern "C" void kernel_launch(void* const* d_in, const int* in_sizes, int n_in,
                              void* d_out, int out_size) {
    const float* feat    = (const float*)d_in[0];
    const int*   src     = (const int*)d_in[1];
    const int*   dst     = (const int*)d_in[2];
    const float* Wfc     = (const float*)d_in[3];
    const float* attn_l  = (const float*)d_in[4];
    const float* attn_r  = (const float*)d_in[5];
    const float* Wres    = (const float*)d_in[6];
    const float* biasg   = (const float*)d_in[7];
    const float* gamma   = (const float*)d_in[8];
    const float* beta    = (const float*)d_in[9];
    const float* Wout    = (const float*)d_in[10];
    const float* bout    = (const float*)d_in[11];
    float* out = (float*)d_out;

    zero_deg_kernel<<<SCAN_NB, 256>>>();
    pvec_kernel<<<8, 128>>>(Wfc, attn_l, attn_r);
    elr_kernel<<<(N_NODES + 7) / 8, 256>>>(feat);
    hist_kernel<<<(N_EDGES + 255) / 256, 256>>>(dst);
    scan1_kernel<<<SCAN_NB, 256>>>();
    scan2_kernel<<<1, 1>>>();
    scan3_kernel<<<SCAN_NB, 256>>>();
    scatter_kernel<<<(N_EDGES + 255) / 256, 256>>>(src, dst);
    dim3 g1(8, (N_NODES + 127) / 128);
    gemm1_kernel<<<g1, 256>>>(feat, Wfc, Wres, biasg);
    agg_kernel<<<(N_NODES + 7) / 8, 256>>>();
    bn_part_kernel<<<BN_BLOCKS, HD>>>();
    bn_final_kernel<<<1, HD>>>(gamma, beta);
    gemm2_kernel<<<(N_NODES + 127) / 128, 256>>>(Wout, bout, out);
}

// round 4
// speedup vs baseline: 1.6347x; 1.6347x over previous
#include <cuda_runtime.h>
#include <cuda_bf16.h>
#include <math.h>
#include <stdint.h>

#define N_NODES 30000
#define N_EDGES 480000
#define NHEAD   4
#define HD      512
#define OUTF    128
#define NEG_SLOPE 0.2f
#define BN_EPS  1e-5f
#define BN_BLOCKS 256
#define SCAN_NB 118

// ---------------- scratch ----------------
__device__ float g_h[N_NODES * HD];
__device__ float g_rst[N_NODES * HD];
__device__ float g_el[N_NODES * NHEAD];
__device__ float g_er[N_NODES * NHEAD];
__device__ float g_P[8 * 128];
__device__ int   g_deg[N_NODES];
__device__ int   g_cursor[N_NODES];
__device__ int   g_ptr[N_NODES + 1];
__device__ int   g_srcs[N_EDGES];
__device__ int   g_blocksum[SCAN_NB];
__device__ int   g_blockoff[SCAN_NB];
__device__ float g_psum[BN_BLOCKS * HD];
__device__ float g_psq[BN_BLOCKS * HD];
__device__ float g_scale[HD];
__device__ float g_shift[HD];
// split-bf16 operands
__device__ unsigned short g_fhi[N_NODES * 128];   // feat hi
__device__ unsigned short g_flo[N_NODES * 128];   // feat lo
__device__ unsigned short g_WT1hi[1024 * 128];    // [n][k] for [Wfc|Wres]
__device__ unsigned short g_WT1lo[1024 * 128];
__device__ unsigned short g_WT2hi[128 * 512];     // [n][k] for Wout
__device__ unsigned short g_WT2lo[128 * 512];

// ---------------- helpers ----------------
__device__ __forceinline__ uint32_t bf2(float lo, float hi) {
    uint32_t r;
    asm("cvt.rn.bf16x2.f32 %0, %1, %2;" : "=r"(r) : "f"(hi), "f"(lo));
    return r;
}
__device__ __forceinline__ float bf_round(float x) {
    return __bfloat162float(__float2bfloat16(x));
}
__device__ __forceinline__ unsigned short bf_hi_us(float x) {
    __nv_bfloat16 b = __float2bfloat16(x);
    return *(unsigned short*)&b;
}
__device__ __forceinline__ unsigned short bf_lo_us(float x) {
    __nv_bfloat16 b = __float2bfloat16(x - bf_round(x));
    return *(unsigned short*)&b;
}
__device__ __forceinline__ void mma_bf16(float* c, uint32_t a0, uint32_t a1,
                                         uint32_t a2, uint32_t a3,
                                         uint32_t b0, uint32_t b1) {
    asm volatile(
        "mma.sync.aligned.m16n8k16.row.col.f32.bf16.bf16.f32 "
        "{%0,%1,%2,%3}, {%4,%5,%6,%7}, {%8,%9}, {%0,%1,%2,%3};"
        : "+f"(c[0]), "+f"(c[1]), "+f"(c[2]), "+f"(c[3])
        : "r"(a0), "r"(a1), "r"(a2), "r"(a3), "r"(b0), "r"(b1));
}

// ---------------- small prep kernels ----------------
__global__ void zero_deg_kernel() {
    int i = blockIdx.x * blockDim.x + threadIdx.x;
    if (i < N_NODES) g_deg[i] = 0;
}

__global__ void split_feat_kernel(const float* __restrict__ feat) {
    int i = blockIdx.x * blockDim.x + threadIdx.x;   // over N*128/4
    if (i >= N_NODES * 32) return;
    float4 v = ((const float4*)feat)[i];
    uint2 hv = make_uint2(bf2(v.x, v.y), bf2(v.z, v.w));
    uint2 lv = make_uint2(bf2(v.x - bf_round(v.x), v.y - bf_round(v.y)),
                          bf2(v.z - bf_round(v.z), v.w - bf_round(v.w)));
    *(uint2*)(g_fhi + i * 4) = hv;
    *(uint2*)(g_flo + i * 4) = lv;
}

// transpose [Wfc|Wres] (128 x 1024 row-major over 512-col halves) -> [1024 n][128 k]
__global__ void transpose1_kernel(const float* __restrict__ Wfc,
                                  const float* __restrict__ Wres) {
    __shared__ float t[32][33];
    int k0 = blockIdx.x * 32;
    int n0 = blockIdx.y * 32;
    int tx = threadIdx.x, ty = threadIdx.y;
    const float* W = (n0 < 512) ? Wfc : Wres;
    int nn0 = (n0 < 512) ? n0 : n0 - 512;
#pragma unroll
    for (int i = 0; i < 32; i += 8)
        t[ty + i][tx] = W[(k0 + ty + i) * 512 + nn0 + tx];
    __syncthreads();
#pragma unroll
    for (int i = 0; i < 32; i += 8) {
        float v = t[tx][ty + i];
        int n = n0 + ty + i, k = k0 + tx;
        g_WT1hi[n * 128 + k] = bf_hi_us(v);
        g_WT1lo[n * 128 + k] = bf_lo_us(v);
    }
}

// transpose Wout (512 x 128) -> [128 n][512 k]
__global__ void transpose2_kernel(const float* __restrict__ Wout) {
    __shared__ float t[32][33];
    int k0 = blockIdx.x * 32;
    int n0 = blockIdx.y * 32;
    int tx = threadIdx.x, ty = threadIdx.y;
#pragma unroll
    for (int i = 0; i < 32; i += 8)
        t[ty + i][tx] = Wout[(k0 + ty + i) * 128 + n0 + tx];
    __syncthreads();
#pragma unroll
    for (int i = 0; i < 32; i += 8) {
        float v = t[tx][ty + i];
        int n = n0 + ty + i, k = k0 + tx;
        g_WT2hi[n * 512 + k] = bf_hi_us(v);
        g_WT2lo[n * 512 + k] = bf_lo_us(v);
    }
}

__global__ void pvec_kernel(const float* __restrict__ Wfc,
                            const float* __restrict__ attn_l,
                            const float* __restrict__ attn_r) {
    int j = blockIdx.x, k = threadIdx.x;
    int h = j & 3;
    const float* av = ((j < 4) ? attn_l : attn_r) + h * 128;
    const float* wr = Wfc + k * HD + h * 128;
    float s = 0.f;
#pragma unroll
    for (int d4 = 0; d4 < 32; d4++) {
        float4 w = *(const float4*)(wr + d4 * 4);
        float4 a = *(const float4*)(av + d4 * 4);
        s += w.x * a.x + w.y * a.y + w.z * a.z + w.w * a.w;
    }
    g_P[j * 128 + k] = s;
}

__global__ __launch_bounds__(256) void elr_kernel(const float* __restrict__ feat) {
    __shared__ float Ps[8][128];
    int t = threadIdx.x;
    for (int i = t; i < 1024; i += 256) Ps[i >> 7][i & 127] = g_P[i];
    __syncthreads();
    int n = blockIdx.x * 8 + (t >> 5);
    int lane = t & 31;
    if (n >= N_NODES) return;
    float4 f = *(const float4*)(feat + n * 128 + lane * 4);
    float s[8];
#pragma unroll
    for (int j = 0; j < 8; j++) {
        const float* p = &Ps[j][lane * 4];
        s[j] = f.x * p[0] + f.y * p[1] + f.z * p[2] + f.w * p[3];
    }
#pragma unroll
    for (int o = 16; o; o >>= 1)
#pragma unroll
        for (int j = 0; j < 8; j++) s[j] += __shfl_xor_sync(0xffffffffu, s[j], o);
    if (lane < 4) {
        g_el[n * 4 + lane] = s[lane];
        g_er[n * 4 + lane] = s[lane + 4];
    }
}

// ---------------- CSR build ----------------
__global__ void hist_kernel(const int* __restrict__ dst) {
    int e = blockIdx.x * blockDim.x + threadIdx.x;
    if (e < N_EDGES) atomicAdd(&g_deg[dst[e]], 1);
}

__global__ void scan1_kernel() {
    __shared__ int wsum[8];
    int t = threadIdx.x, b = blockIdx.x;
    int idx = b * 256 + t;
    int lane = t & 31, wid = t >> 5;
    int v = (idx < N_NODES) ? g_deg[idx] : 0;
    int x = v;
#pragma unroll
    for (int o = 1; o < 32; o <<= 1) {
        int y = __shfl_up_sync(0xffffffffu, x, o);
        if (lane >= o) x += y;
    }
    if (lane == 31) wsum[wid] = x;
    __syncthreads();
    if (t == 0) {
        int run = 0;
#pragma unroll
        for (int i = 0; i < 8; i++) { int tmp = wsum[i]; wsum[i] = run; run += tmp; }
        g_blocksum[b] = run;
    }
    __syncthreads();
    int incl = x + wsum[wid];
    if (idx < N_NODES) g_ptr[idx + 1] = incl;
}

__global__ void scan2_kernel() {
    int run = 0;
    for (int i = 0; i < SCAN_NB; i++) {
        int tmp = g_blocksum[i];
        g_blockoff[i] = run;
        run += tmp;
    }
}

__global__ void scan3_kernel() {
    int t = threadIdx.x, b = blockIdx.x;
    int idx = b * 256 + t;
    if (idx >= N_NODES) return;
    int off = g_blockoff[b];
    int incl = g_ptr[idx + 1] + off;
    g_ptr[idx + 1] = incl;
    g_cursor[idx] = incl - g_deg[idx];
    if (idx == 0) g_ptr[0] = 0;
}

__global__ void scatter_kernel(const int* __restrict__ src,
                               const int* __restrict__ dst) {
    int e = blockIdx.x * blockDim.x + threadIdx.x;
    if (e < N_EDGES) {
        int p = atomicAdd(&g_cursor[dst[e]], 1);
        g_srcs[p] = src[e];
    }
}

// ---------------- GEMM1 (mma.sync): g_h / g_rst = feat @ [Wfc|Wres] ----------
// block 128 rows x 128 cols, BK=32, 8 warps each 64x32 (4x4 m16n8 tiles)
#define AS 40   // bf16 stride (20 b32)
__global__ __launch_bounds__(256) void gemm1_mma(const float* __restrict__ biasg) {
    __shared__ unsigned short Ah[128 * AS], Al[128 * AS];
    __shared__ unsigned short Bh[128 * AS], Bl[128 * AS];
    const int tid = threadIdx.x;
    const int warp = tid >> 5, lane = tid & 31;
    const int wm = warp >> 2, wn = warp & 3;
    const int g = lane >> 2, t = lane & 3;
    const int row0 = blockIdx.y * 128;
    const int bx = blockIdx.x;

    float c[4][4][4];
#pragma unroll
    for (int i = 0; i < 4; i++)
#pragma unroll
        for (int j = 0; j < 4; j++)
#pragma unroll
            for (int q = 0; q < 4; q++) c[i][j][q] = 0.f;

    for (int kc = 0; kc < 4; kc++) {
        int k0 = kc * 32;
#pragma unroll
        for (int l = 0; l < 4; l++) {
            int i = tid + l * 256;          // 0..1023
            int r = i >> 3, k4 = i & 7;
            int gr = row0 + r;
            uint2 hv = make_uint2(0u, 0u), lv = make_uint2(0u, 0u);
            if (gr < N_NODES) {
                hv = *(const uint2*)(g_fhi + gr * 128 + k0 + k4 * 4);
                lv = *(const uint2*)(g_flo + gr * 128 + k0 + k4 * 4);
            }
            *(uint2*)(Ah + r * AS + k4 * 4) = hv;
            *(uint2*)(Al + r * AS + k4 * 4) = lv;
            int n = bx * 128 + r;
            *(uint2*)(Bh + r * AS + k4 * 4) =
                *(const uint2*)(g_WT1hi + n * 128 + k0 + k4 * 4);
            *(uint2*)(Bl + r * AS + k4 * 4) =
                *(const uint2*)(g_WT1lo + n * 128 + k0 + k4 * 4);
        }
        __syncthreads();
        const uint32_t* Ah32 = (const uint32_t*)Ah;
        const uint32_t* Al32 = (const uint32_t*)Al;
        const uint32_t* Bh32 = (const uint32_t*)Bh;
        const uint32_t* Bl32 = (const uint32_t*)Bl;
#pragma unroll
        for (int ks = 0; ks < 2; ks++) {
            int kb = ks * 8;
            uint32_t ah[4][4], al[4][4], bh[4][2], bl[4][2];
#pragma unroll
            for (int rb = 0; rb < 4; rb++) {
                int base = (wm * 64 + rb * 16 + g) * 20 + kb + t;
                ah[rb][0] = Ah32[base];       ah[rb][1] = Ah32[base + 160];
                ah[rb][2] = Ah32[base + 4];   ah[rb][3] = Ah32[base + 164];
                al[rb][0] = Al32[base];       al[rb][1] = Al32[base + 160];
                al[rb][2] = Al32[base + 4];   al[rb][3] = Al32[base + 164];
            }
#pragma unroll
            for (int nb = 0; nb < 4; nb++) {
                int base = (wn * 32 + nb * 8 + g) * 20 + kb + t;
                bh[nb][0] = Bh32[base];  bh[nb][1] = Bh32[base + 4];
                bl[nb][0] = Bl32[base];  bl[nb][1] = Bl32[base + 4];
            }
#pragma unroll
            for (int rb = 0; rb < 4; rb++)
#pragma unroll
                for (int nb = 0; nb < 4; nb++) {
                    mma_bf16(c[rb][nb], ah[rb][0], ah[rb][1], ah[rb][2], ah[rb][3],
                             bh[nb][0], bh[nb][1]);
                    mma_bf16(c[rb][nb], al[rb][0], al[rb][1], al[rb][2], al[rb][3],
                             bh[nb][0], bh[nb][1]);
                    mma_bf16(c[rb][nb], ah[rb][0], ah[rb][1], ah[rb][2], ah[rb][3],
                             bl[nb][0], bl[nb][1]);
                }
        }
        __syncthreads();
    }
    // epilogue
#pragma unroll
    for (int rb = 0; rb < 4; rb++) {
        int gr0 = row0 + wm * 64 + rb * 16 + g;
#pragma unroll
        for (int nb = 0; nb < 4; nb++) {
            int col = bx * 128 + wn * 32 + nb * 8 + 2 * t;
            float* cc = c[rb][nb];
            if (col < 512) {
                if (gr0 < N_NODES)
                    *(float2*)(g_h + gr0 * HD + col) = make_float2(cc[0], cc[1]);
                if (gr0 + 8 < N_NODES)
                    *(float2*)(g_h + (gr0 + 8) * HD + col) = make_float2(cc[2], cc[3]);
            } else {
                int cb = col - 512;
                float2 bv = *(const float2*)(biasg + cb);
                if (gr0 < N_NODES)
                    *(float2*)(g_rst + gr0 * HD + cb) =
                        make_float2(cc[0] + bv.x, cc[1] + bv.y);
                if (gr0 + 8 < N_NODES)
                    *(float2*)(g_rst + (gr0 + 8) * HD + cb) =
                        make_float2(cc[2] + bv.x, cc[3] + bv.y);
            }
        }
    }
}

// ---------------- aggregation: one warp per node, 4 heads ----------------
__global__ __launch_bounds__(256) void agg_kernel() {
    int v = blockIdx.x * 8 + (threadIdx.x >> 5);
    int lane = threadIdx.x & 31;
    if (v >= N_NODES) return;
    int start = g_ptr[v], end = g_ptr[v + 1];
    if (start == end) return;
    float4 er = *(const float4*)(g_er + v * 4);

    float4 a0 = make_float4(0.f, 0.f, 0.f, 0.f);
    float4 a1 = a0, a2 = a0, a3 = a0;
    float d0 = 0.f, d1 = 0.f, d2 = 0.f, d3 = 0.f;

    for (int j = start; j < end; j++) {
        int s = g_srcs[j];
        float4 el = *(const float4*)(g_el + s * 4);
        const float* hp = g_h + s * HD + lane * 4;
        float4 h0 = *(const float4*)(hp);
        float4 h1 = *(const float4*)(hp + 128);
        float4 h2 = *(const float4*)(hp + 256);
        float4 h3 = *(const float4*)(hp + 384);
        float e0 = el.x + er.x; e0 = (e0 > 0.f) ? e0 : NEG_SLOPE * e0;
        float e1 = el.y + er.y; e1 = (e1 > 0.f) ? e1 : NEG_SLOPE * e1;
        float e2 = el.z + er.z; e2 = (e2 > 0.f) ? e2 : NEG_SLOPE * e2;
        float e3 = el.w + er.w; e3 = (e3 > 0.f) ? e3 : NEG_SLOPE * e3;
        float w0 = __expf(e0), w1 = __expf(e1), w2 = __expf(e2), w3 = __expf(e3);
        d0 += w0; d1 += w1; d2 += w2; d3 += w3;
        a0.x += w0 * h0.x; a0.y += w0 * h0.y; a0.z += w0 * h0.z; a0.w += w0 * h0.w;
        a1.x += w1 * h1.x; a1.y += w1 * h1.y; a1.z += w1 * h1.z; a1.w += w1 * h1.w;
        a2.x += w2 * h2.x; a2.y += w2 * h2.y; a2.z += w2 * h2.z; a2.w += w2 * h2.w;
        a3.x += w3 * h3.x; a3.y += w3 * h3.y; a3.z += w3 * h3.z; a3.w += w3 * h3.w;
    }
    float i0 = 1.f / d0, i1 = 1.f / d1, i2 = 1.f / d2, i3 = 1.f / d3;
    float* o = g_rst + v * HD + lane * 4;
    float4 c0 = *(float4*)(o);
    float4 c1 = *(float4*)(o + 128);
    float4 c2 = *(float4*)(o + 256);
    float4 c3 = *(float4*)(o + 384);
    c0.x += a0.x * i0; c0.y += a0.y * i0; c0.z += a0.z * i0; c0.w += a0.w * i0;
    c1.x += a1.x * i1; c1.y += a1.y * i1; c1.z += a1.z * i1; c1.w += a1.w * i1;
    c2.x += a2.x * i2; c2.y += a2.y * i2; c2.z += a2.z * i2; c2.w += a2.w * i2;
    c3.x += a3.x * i3; c3.y += a3.y * i3; c3.z += a3.z * i3; c3.w += a3.w * i3;
    *(float4*)(o)       = c0;
    *(float4*)(o + 128) = c1;
    *(float4*)(o + 256) = c2;
    *(float4*)(o + 384) = c3;
}

// ---------------- BatchNorm stats ----------------
__global__ void bn_part_kernel() {
    int c = threadIdx.x;
    float s = 0.f, q = 0.f;
    for (int r = blockIdx.x; r < N_NODES; r += gridDim.x) {
        float x = g_rst[r * HD + c];
        s += x;
        q += x * x;
    }
    g_psum[blockIdx.x * HD + c] = s;
    g_psq[blockIdx.x * HD + c] = q;
}

__global__ void bn_final_kernel(const float* __restrict__ gamma,
                                const float* __restrict__ beta) {
    int c = threadIdx.x;
    float s = 0.f, q = 0.f;
    for (int b = 0; b < BN_BLOCKS; b++) {
        s += g_psum[b * HD + c];
        q += g_psq[b * HD + c];
    }
    float mu = s / (float)N_NODES;
    float var = q / (float)N_NODES - mu * mu;
    float rstd = rsqrtf(var + BN_EPS);
    float sc = gamma[c] * rstd;
    g_scale[c] = sc;
    g_shift[c] = beta[c] - mu * sc;
}

// ---------------- GEMM2 (mma.sync): out = ReLU(BN(rst)) @ W_out + b_out ------
__global__ __launch_bounds__(256) void gemm2_mma(const float* __restrict__ bout,
                                                 float* __restrict__ out) {
    __shared__ unsigned short Ah[128 * AS], Al[128 * AS];
    __shared__ unsigned short Bh[128 * AS], Bl[128 * AS];
    const int tid = threadIdx.x;
    const int warp = tid >> 5, lane = tid & 31;
    const int wm = warp >> 2, wn = warp & 3;
    const int g = lane >> 2, t = lane & 3;
    const int row0 = blockIdx.x * 128;

    float c[4][4][4];
#pragma unroll
    for (int i = 0; i < 4; i++)
#pragma unroll
        for (int j = 0; j < 4; j++)
#pragma unroll
            for (int q = 0; q < 4; q++) c[i][j][q] = 0.f;

    for (int kc = 0; kc < 16; kc++) {
        int k0 = kc * 32;
#pragma unroll
        for (int l = 0; l < 4; l++) {
            int i = tid + l * 256;
            int r = i >> 3, k4 = i & 7;
            int gr = row0 + r;
            int col = k0 + k4 * 4;
            float4 v = make_float4(0.f, 0.f, 0.f, 0.f);
            if (gr < N_NODES) {
                float4 x = *(const float4*)(g_rst + gr * HD + col);
                float4 sc = *(const float4*)(g_scale + col);
                float4 sh = *(const float4*)(g_shift + col);
                v.x = fmaxf(sc.x * x.x + sh.x, 0.f);
                v.y = fmaxf(sc.y * x.y + sh.y, 0.f);
                v.z = fmaxf(sc.z * x.z + sh.z, 0.f);
                v.w = fmaxf(sc.w * x.w + sh.w, 0.f);
            }
            *(uint2*)(Ah + r * AS + k4 * 4) =
                make_uint2(bf2(v.x, v.y), bf2(v.z, v.w));
            *(uint2*)(Al + r * AS + k4 * 4) =
                make_uint2(bf2(v.x - bf_round(v.x), v.y - bf_round(v.y)),
                           bf2(v.z - bf_round(v.z), v.w - bf_round(v.w)));
            *(uint2*)(Bh + r * AS + k4 * 4) =
                *(const uint2*)(g_WT2hi + r * 512 + col);
            *(uint2*)(Bl + r * AS + k4 * 4) =
                *(const uint2*)(g_WT2lo + r * 512 + col);
        }
        __syncthreads();
        const uint32_t* Ah32 = (const uint32_t*)Ah;
        const uint32_t* Al32 = (const uint32_t*)Al;
        const uint32_t* Bh32 = (const uint32_t*)Bh;
        const uint32_t* Bl32 = (const uint32_t*)Bl;
#pragma unroll
        for (int ks = 0; ks < 2; ks++) {
            int kb = ks * 8;
            uint32_t ah[4][4], al[4][4], bh[4][2], bl[4][2];
#pragma unroll
            for (int rb = 0; rb < 4; rb++) {
                int base = (wm * 64 + rb * 16 + g) * 20 + kb + t;
                ah[rb][0] = Ah32[base];       ah[rb][1] = Ah32[base + 160];
                ah[rb][2] = Ah32[base + 4];   ah[rb][3] = Ah32[base + 164];
                al[rb][0] = Al32[base];       al[rb][1] = Al32[base + 160];
                al[rb][2] = Al32[base + 4];   al[rb][3] = Al32[base + 164];
            }
#pragma unroll
            for (int nb = 0; nb < 4; nb++) {
                int base = (wn * 32 + nb * 8 + g) * 20 + kb + t;
                bh[nb][0] = Bh32[base];  bh[nb][1] = Bh32[base + 4];
                bl[nb][0] = Bl32[base];  bl[nb][1] = Bl32[base + 4];
            }
#pragma unroll
            for (int rb = 0; rb < 4; rb++)
#pragma unroll
                for (int nb = 0; nb < 4; nb++) {
                    mma_bf16(c[rb][nb], ah[rb][0], ah[rb][1], ah[rb][2], ah[rb][3],
                             bh[nb][0], bh[nb][1]);
                    mma_bf16(c[rb][nb], al[rb][0], al[rb][1], al[rb][2], al[rb][3],
                             bh[nb][0], bh[nb][1]);
                    mma_bf16(c[rb][nb], ah[rb][0], ah[rb][1], ah[rb][2], ah[rb][3],
                             bl[nb][0], bl[nb][1]);
                }
        }
        __syncthreads();
    }
#pragma unroll
    for (int rb = 0; rb < 4; rb++) {
        int gr0 = row0 + wm * 64 + rb * 16 + g;
#pragma unroll
        for (int nb = 0; nb < 4; nb++) {
            int col = wn * 32 + nb * 8 + 2 * t;
            float* cc = c[rb][nb];
            float2 bv = *(const float2*)(bout + col);
            if (gr0 < N_NODES)
                *(float2*)(out + gr0 * OUTF + col) =
                    make_float2(cc[0] + bv.x, cc[1] + bv.y);
            if (gr0 + 8 < N_NODES)
                *(float2*)(out + (gr0 + 8) * OUTF + col) =
                    make_float2(cc[2] + bv.x, cc[3] + bv.y);
        }
    }
}

// ---------------- launch ----------------
extern "C" void kernel_launch(void* const* d_in, const int* in_sizes, int n_in,
                              void* d_out, int out_size) {
    const float* feat    = (const float*)d_in[0];
    const int*   src     = (const int*)d_in[1];
    const int*   dst     = (const int*)d_in[2];
    const float* Wfc     = (const float*)d_in[3];
    const float* attn_l  = (const float*)d_in[4];
    const float* attn_r  = (const float*)d_in[5];
    const float* Wres    = (const float*)d_in[6];
    const float* biasg   = (const float*)d_in[7];
    const float* gamma   = (const float*)d_in[8];
    const float* beta    = (const float*)d_in[9];
    const float* Wout    = (const float*)d_in[10];
    const float* bout    = (const float*)d_in[11];
    float* out = (float*)d_out;

    zero_deg_kernel<<<SCAN_NB, 256>>>();
    split_feat_kernel<<<(N_NODES * 32 + 255) / 256, 256>>>(feat);
    transpose1_kernel<<<dim3(4, 32), dim3(32, 8)>>>(Wfc, Wres);
    transpose2_kernel<<<dim3(16, 4), dim3(32, 8)>>>(Wout);
    pvec_kernel<<<8, 128>>>(Wfc, attn_l, attn_r);
    elr_kernel<<<(N_NODES + 7) / 8, 256>>>(feat);
    hist_kernel<<<(N_EDGES + 255) / 256, 256>>>(dst);
    scan1_kernel<<<SCAN_NB, 256>>>();
    scan2_kernel<<<1, 1>>>();
    scan3_kernel<<<SCAN_NB, 256>>>();
    scatter_kernel<<<(N_EDGES + 255) / 256, 256>>>(src, dst);
    gemm1_mma<<<dim3(8, (N_NODES + 127) / 128), 256>>>(biasg);
    agg_kernel<<<(N_NODES + 7) / 8, 256>>>();
    bn_part_kernel<<<BN_BLOCKS, HD>>>();
    bn_final_kernel<<<1, HD>>>(gamma, beta);
    gemm2_mma<<<(N_NODES + 127) / 128, 256>>>(bout, out);
}

// round 5
// speedup vs baseline: 1.6465x; 1.0072x over previous
#include <cuda_runtime.h>
#include <cuda_bf16.h>
#include <math.h>
#include <stdint.h>

#define N_NODES 30000
#define N_EDGES 480000
#define NHEAD   4
#define HD      512
#define OUTF    128
#define NEG_SLOPE 0.2f
#define BN_EPS  1e-5f
#define BN_BLOCKS 256
#define SCAN_NB 118
#define NROWB   235          // ceil(30000/128)

// ---------------- scratch ----------------
__device__ float g_h[N_NODES * HD];
__device__ float g_rst[N_NODES * HD];
__device__ float g_el[N_NODES * NHEAD];
__device__ float g_er[N_NODES * NHEAD];
__device__ float g_P[8 * 128];
__device__ int   g_deg[N_NODES];
__device__ int   g_cursor[N_NODES];
__device__ int   g_ptr[N_NODES + 1];
__device__ int   g_srcs[N_EDGES];
__device__ int   g_blocksum[SCAN_NB];
__device__ int   g_blockoff[SCAN_NB];
__device__ float g_psum[BN_BLOCKS * HD];
__device__ float g_psq[BN_BLOCKS * HD];
__device__ float g_scale[HD];
__device__ float g_shift[HD];
__device__ unsigned short g_WT1hi[1024 * 128];    // [n][k] for [Wfc|Wres]
__device__ unsigned short g_WT1lo[1024 * 128];
__device__ unsigned short g_WT2hi[128 * 512];     // [n][k] for Wout
__device__ unsigned short g_WT2lo[128 * 512];

// ---------------- helpers ----------------
__device__ __forceinline__ uint32_t bf2(float lo, float hi) {
    uint32_t r;
    asm("cvt.rn.bf16x2.f32 %0, %1, %2;" : "=r"(r) : "f"(hi), "f"(lo));
    return r;
}
__device__ __forceinline__ float bf_round(float x) {
    return __bfloat162float(__float2bfloat16(x));
}
__device__ __forceinline__ unsigned short bf_hi_us(float x) {
    __nv_bfloat16 b = __float2bfloat16(x);
    return *(unsigned short*)&b;
}
__device__ __forceinline__ unsigned short bf_lo_us(float x) {
    __nv_bfloat16 b = __float2bfloat16(x - bf_round(x));
    return *(unsigned short*)&b;
}
__device__ __forceinline__ void mma_bf16(float* c, uint32_t a0, uint32_t a1,
                                         uint32_t a2, uint32_t a3,
                                         uint32_t b0, uint32_t b1) {
    asm volatile(
        "mma.sync.aligned.m16n8k16.row.col.f32.bf16.bf16.f32 "
        "{%0,%1,%2,%3}, {%4,%5,%6,%7}, {%8,%9}, {%0,%1,%2,%3};"
        : "+f"(c[0]), "+f"(c[1]), "+f"(c[2]), "+f"(c[3])
        : "r"(a0), "r"(a1), "r"(a2), "r"(a3), "r"(b0), "r"(b1));
}

// ---------------- fused prep: zero_deg | transpose1 | transpose2 | pvec ------
__global__ __launch_bounds__(256) void prep_kernel(
    const float* __restrict__ Wfc, const float* __restrict__ Wres,
    const float* __restrict__ Wout, const float* __restrict__ attn_l,
    const float* __restrict__ attn_r) {
    int b = blockIdx.x;
    int tid = threadIdx.x;
    if (b < SCAN_NB) {                                  // zero degree
        int i = b * 256 + tid;
        if (i < N_NODES) g_deg[i] = 0;
        return;
    }
    b -= SCAN_NB;
    if (b < 128) {                                      // transpose [Wfc|Wres]
        __shared__ float t[32][33];
        int k0 = (b & 3) * 32;
        int n0 = (b >> 2) * 32;
        int tx = tid & 31, ty = tid >> 5;
        const float* W = (n0 < 512) ? Wfc : Wres;
        int nn0 = (n0 < 512) ? n0 : n0 - 512;
#pragma unroll
        for (int i = 0; i < 32; i += 8)
            t[ty + i][tx] = W[(k0 + ty + i) * 512 + nn0 + tx];
        __syncthreads();
#pragma unroll
        for (int i = 0; i < 32; i += 8) {
            float v = t[tx][ty + i];
            int n = n0 + ty + i, k = k0 + tx;
            g_WT1hi[n * 128 + k] = bf_hi_us(v);
            g_WT1lo[n * 128 + k] = bf_lo_us(v);
        }
        return;
    }
    b -= 128;
    if (b < 64) {                                       // transpose Wout
        __shared__ float t2[32][33];
        int k0 = (b & 15) * 32;
        int n0 = (b >> 4) * 32;
        int tx = tid & 31, ty = tid >> 5;
#pragma unroll
        for (int i = 0; i < 32; i += 8)
            t2[ty + i][tx] = Wout[(k0 + ty + i) * 128 + n0 + tx];
        __syncthreads();
#pragma unroll
        for (int i = 0; i < 32; i += 8) {
            float v = t2[tx][ty + i];
            int n = n0 + ty + i, k = k0 + tx;
            g_WT2hi[n * 512 + k] = bf_hi_us(v);
            g_WT2lo[n * 512 + k] = bf_lo_us(v);
        }
        return;
    }
    b -= 64;                                            // pvec: 8 blocks
    if (tid >= 128) return;
    int h = b & 3;
    const float* av = ((b < 4) ? attn_l : attn_r) + h * 128;
    const float* wr = Wfc + tid * HD + h * 128;
    float s = 0.f;
#pragma unroll
    for (int d4 = 0; d4 < 32; d4++) {
        float4 w = *(const float4*)(wr + d4 * 4);
        float4 a = *(const float4*)(av + d4 * 4);
        s += w.x * a.x + w.y * a.y + w.z * a.z + w.w * a.w;
    }
    g_P[b * 128 + tid] = s;
}

__global__ __launch_bounds__(256) void elr_kernel(const float* __restrict__ feat) {
    __shared__ float Ps[8][128];
    int t = threadIdx.x;
    for (int i = t; i < 1024; i += 256) Ps[i >> 7][i & 127] = g_P[i];
    __syncthreads();
    int n = blockIdx.x * 8 + (t >> 5);
    int lane = t & 31;
    if (n >= N_NODES) return;
    float4 f = *(const float4*)(feat + n * 128 + lane * 4);
    float s[8];
#pragma unroll
    for (int j = 0; j < 8; j++) {
        const float* p = &Ps[j][lane * 4];
        s[j] = f.x * p[0] + f.y * p[1] + f.z * p[2] + f.w * p[3];
    }
#pragma unroll
    for (int o = 16; o; o >>= 1)
#pragma unroll
        for (int j = 0; j < 8; j++) s[j] += __shfl_xor_sync(0xffffffffu, s[j], o);
    if (lane < 4) {
        g_el[n * 4 + lane] = s[lane];
        g_er[n * 4 + lane] = s[lane + 4];
    }
}

// ---------------- CSR build ----------------
__global__ void hist_kernel(const int* __restrict__ dst) {
    int e = blockIdx.x * blockDim.x + threadIdx.x;
    if (e < N_EDGES) atomicAdd(&g_deg[dst[e]], 1);
}

__global__ void scan1_kernel() {
    __shared__ int wsum[8];
    int t = threadIdx.x, b = blockIdx.x;
    int idx = b * 256 + t;
    int lane = t & 31, wid = t >> 5;
    int v = (idx < N_NODES) ? g_deg[idx] : 0;
    int x = v;
#pragma unroll
    for (int o = 1; o < 32; o <<= 1) {
        int y = __shfl_up_sync(0xffffffffu, x, o);
        if (lane >= o) x += y;
    }
    if (lane == 31) wsum[wid] = x;
    __syncthreads();
    if (t == 0) {
        int run = 0;
#pragma unroll
        for (int i = 0; i < 8; i++) { int tmp = wsum[i]; wsum[i] = run; run += tmp; }
        g_blocksum[b] = run;
    }
    __syncthreads();
    int incl = x + wsum[wid];
    if (idx < N_NODES) g_ptr[idx + 1] = incl;
}

__global__ void scan2_kernel() {
    int run = 0;
    for (int i = 0; i < SCAN_NB; i++) {
        int tmp = g_blocksum[i];
        g_blockoff[i] = run;
        run += tmp;
    }
}

__global__ void scan3_kernel() {
    int t = threadIdx.x, b = blockIdx.x;
    int idx = b * 256 + t;
    if (idx >= N_NODES) return;
    int off = g_blockoff[b];
    int incl = g_ptr[idx + 1] + off;
    g_ptr[idx + 1] = incl;
    g_cursor[idx] = incl - g_deg[idx];
    if (idx == 0) g_ptr[0] = 0;
}

__global__ void scatter_kernel(const int* __restrict__ src,
                               const int* __restrict__ dst) {
    int e = blockIdx.x * blockDim.x + threadIdx.x;
    if (e < N_EDGES) {
        int p = atomicAdd(&g_cursor[dst[e]], 1);
        g_srcs[p] = src[e];
    }
}

// ---------------- GEMM1 (mma.sync, full-K smem, 4 n-blocks per CTA) ---------
// A: 128 rows x 128 k (bf16 hi/lo), stride 136 shorts (68 b32) — banks 4g+t CF.
#define KS1 136
#define KS1_32 68
#define SMEM_G (4 * 128 * KS1 * 2)   // 139264 bytes

__global__ __launch_bounds__(256) void gemm1_mma(const float* __restrict__ feat,
                                                 const float* __restrict__ biasg) {
    extern __shared__ unsigned short sm[];
    unsigned short* Ah = sm;
    unsigned short* Al = Ah + 128 * KS1;
    unsigned short* Bh = Al + 128 * KS1;
    unsigned short* Bl = Bh + 128 * KS1;
    const int tid = threadIdx.x;
    const int warp = tid >> 5, lane = tid & 31;
    const int wm = warp >> 2, wn = warp & 3;
    const int g = lane >> 2, t = lane & 3;
    const int row0 = blockIdx.y * 128;
    const int half = blockIdx.x;           // 0: cols 0..511 (g_h), 1: 512..1023 (g_rst)

    // fill A once: feat fp32 -> split bf16
    for (int idx = tid; idx < 4096; idx += 256) {
        int r = idx >> 5, k4 = idx & 31;
        int gr = row0 + r;
        float4 f = make_float4(0.f, 0.f, 0.f, 0.f);
        if (gr < N_NODES) f = *(const float4*)(feat + gr * 128 + k4 * 4);
        *(uint2*)(Ah + r * KS1 + k4 * 4) = make_uint2(bf2(f.x, f.y), bf2(f.z, f.w));
        *(uint2*)(Al + r * KS1 + k4 * 4) =
            make_uint2(bf2(f.x - bf_round(f.x), f.y - bf_round(f.y)),
                       bf2(f.z - bf_round(f.z), f.w - bf_round(f.w)));
    }

    const uint32_t* Ah32 = (const uint32_t*)Ah;
    const uint32_t* Al32 = (const uint32_t*)Al;
    const uint32_t* Bh32 = (const uint32_t*)Bh;
    const uint32_t* Bl32 = (const uint32_t*)Bl;

    for (int i = 0; i < 4; i++) {
        int bx = half * 4 + i;
        // fill B for this n-block
        for (int idx = tid; idx < 4096; idx += 256) {
            int r = idx >> 5, k4 = idx & 31;
            int n = bx * 128 + r;
            *(uint2*)(Bh + r * KS1 + k4 * 4) = *(const uint2*)(g_WT1hi + n * 128 + k4 * 4);
            *(uint2*)(Bl + r * KS1 + k4 * 4) = *(const uint2*)(g_WT1lo + n * 128 + k4 * 4);
        }
        __syncthreads();   // A (first iter) + B ready

        float c[4][4][4];
#pragma unroll
        for (int a = 0; a < 4; a++)
#pragma unroll
            for (int bq = 0; bq < 4; bq++)
#pragma unroll
                for (int q = 0; q < 4; q++) c[a][bq][q] = 0.f;

#pragma unroll
        for (int ks = 0; ks < 8; ks++) {
            int kb = ks * 8;
            uint32_t ah[4][4], al[4][4], bh[4][2], bl[4][2];
#pragma unroll
            for (int rb = 0; rb < 4; rb++) {
                int base = (wm * 64 + rb * 16 + g) * KS1_32 + kb + t;
                ah[rb][0] = Ah32[base];             ah[rb][1] = Ah32[base + 8 * KS1_32];
                ah[rb][2] = Ah32[base + 4];         ah[rb][3] = Ah32[base + 8 * KS1_32 + 4];
                al[rb][0] = Al32[base];             al[rb][1] = Al32[base + 8 * KS1_32];
                al[rb][2] = Al32[base + 4];         al[rb][3] = Al32[base + 8 * KS1_32 + 4];
            }
#pragma unroll
            for (int nb = 0; nb < 4; nb++) {
                int base = (wn * 32 + nb * 8 + g) * KS1_32 + kb + t;
                bh[nb][0] = Bh32[base];  bh[nb][1] = Bh32[base + 4];
                bl[nb][0] = Bl32[base];  bl[nb][1] = Bl32[base + 4];
            }
#pragma unroll
            for (int rb = 0; rb < 4; rb++)
#pragma unroll
                for (int nb = 0; nb < 4; nb++) {
                    mma_bf16(c[rb][nb], ah[rb][0], ah[rb][1], ah[rb][2], ah[rb][3],
                             bh[nb][0], bh[nb][1]);
                    mma_bf16(c[rb][nb], al[rb][0], al[rb][1], al[rb][2], al[rb][3],
                             bh[nb][0], bh[nb][1]);
                    mma_bf16(c[rb][nb], ah[rb][0], ah[rb][1], ah[rb][2], ah[rb][3],
                             bl[nb][0], bl[nb][1]);
                }
        }
        // epilogue for this n-block
#pragma unroll
        for (int rb = 0; rb < 4; rb++) {
            int gr0 = row0 + wm * 64 + rb * 16 + g;
#pragma unroll
            for (int nb = 0; nb < 4; nb++) {
                int col = bx * 128 + wn * 32 + nb * 8 + 2 * t;
                float* cc = c[rb][nb];
                if (col < 512) {
                    if (gr0 < N_NODES)
                        *(float2*)(g_h + gr0 * HD + col) = make_float2(cc[0], cc[1]);
                    if (gr0 + 8 < N_NODES)
                        *(float2*)(g_h + (gr0 + 8) * HD + col) = make_float2(cc[2], cc[3]);
                } else {
                    int cb = col - 512;
                    float2 bv = *(const float2*)(biasg + cb);
                    if (gr0 < N_NODES)
                        *(float2*)(g_rst + gr0 * HD + cb) =
                            make_float2(cc[0] + bv.x, cc[1] + bv.y);
                    if (gr0 + 8 < N_NODES)
                        *(float2*)(g_rst + (gr0 + 8) * HD + cb) =
                            make_float2(cc[2] + bv.x, cc[3] + bv.y);
                }
            }
        }
        __syncthreads();   // before overwriting B
    }
}

// ---------------- aggregation (unchanged, validated) ----------------
__global__ __launch_bounds__(256) void agg_kernel() {
    int v = blockIdx.x * 8 + (threadIdx.x >> 5);
    int lane = threadIdx.x & 31;
    if (v >= N_NODES) return;
    int start = g_ptr[v], end = g_ptr[v + 1];
    if (start == end) return;
    float4 er = *(const float4*)(g_er + v * 4);

    float4 a0 = make_float4(0.f, 0.f, 0.f, 0.f);
    float4 a1 = a0, a2 = a0, a3 = a0;
    float d0 = 0.f, d1 = 0.f, d2 = 0.f, d3 = 0.f;

    for (int j = start; j < end; j++) {
        int s = g_srcs[j];
        float4 el = *(const float4*)(g_el + s * 4);
        const float* hp = g_h + s * HD + lane * 4;
        float4 h0 = *(const float4*)(hp);
        float4 h1 = *(const float4*)(hp + 128);
        float4 h2 = *(const float4*)(hp + 256);
        float4 h3 = *(const float4*)(hp + 384);
        float e0 = el.x + er.x; e0 = (e0 > 0.f) ? e0 : NEG_SLOPE * e0;
        float e1 = el.y + er.y; e1 = (e1 > 0.f) ? e1 : NEG_SLOPE * e1;
        float e2 = el.z + er.z; e2 = (e2 > 0.f) ? e2 : NEG_SLOPE * e2;
        float e3 = el.w + er.w; e3 = (e3 > 0.f) ? e3 : NEG_SLOPE * e3;
        float w0 = __expf(e0), w1 = __expf(e1), w2 = __expf(e2), w3 = __expf(e3);
        d0 += w0; d1 += w1; d2 += w2; d3 += w3;
        a0.x += w0 * h0.x; a0.y += w0 * h0.y; a0.z += w0 * h0.z; a0.w += w0 * h0.w;
        a1.x += w1 * h1.x; a1.y += w1 * h1.y; a1.z += w1 * h1.z; a1.w += w1 * h1.w;
        a2.x += w2 * h2.x; a2.y += w2 * h2.y; a2.z += w2 * h2.z; a2.w += w2 * h2.w;
        a3.x += w3 * h3.x; a3.y += w3 * h3.y; a3.z += w3 * h3.z; a3.w += w3 * h3.w;
    }
    float i0 = 1.f / d0, i1 = 1.f / d1, i2 = 1.f / d2, i3 = 1.f / d3;
    float* o = g_rst + v * HD + lane * 4;
    float4 c0 = *(float4*)(o);
    float4 c1 = *(float4*)(o + 128);
    float4 c2 = *(float4*)(o + 256);
    float4 c3 = *(float4*)(o + 384);
    c0.x += a0.x * i0; c0.y += a0.y * i0; c0.z += a0.z * i0; c0.w += a0.w * i0;
    c1.x += a1.x * i1; c1.y += a1.y * i1; c1.z += a1.z * i1; c1.w += a1.w * i1;
    c2.x += a2.x * i2; c2.y += a2.y * i2; c2.z += a2.z * i2; c2.w += a2.w * i2;
    c3.x += a3.x * i3; c3.y += a3.y * i3; c3.z += a3.z * i3; c3.w += a3.w * i3;
    *(float4*)(o)       = c0;
    *(float4*)(o + 128) = c1;
    *(float4*)(o + 256) = c2;
    *(float4*)(o + 384) = c3;
}

// ---------------- BatchNorm stats ----------------
__global__ void bn_part_kernel() {
    int c = threadIdx.x;
    float s = 0.f, q = 0.f;
    for (int r = blockIdx.x; r < N_NODES; r += gridDim.x) {
        float x = g_rst[r * HD + c];
        s += x;
        q += x * x;
    }
    g_psum[blockIdx.x * HD + c] = s;
    g_psq[blockIdx.x * HD + c] = q;
}

__global__ void bn_final_kernel(const float* __restrict__ gamma,
                                const float* __restrict__ beta) {
    int c = threadIdx.x;
    float s = 0.f, q = 0.f;
    for (int b = 0; b < BN_BLOCKS; b++) {
        s += g_psum[b * HD + c];
        q += g_psq[b * HD + c];
    }
    float mu = s / (float)N_NODES;
    float var = q / (float)N_NODES - mu * mu;
    float rstd = rsqrtf(var + BN_EPS);
    float sc = gamma[c] * rstd;
    g_scale[c] = sc;
    g_shift[c] = beta[c] - mu * sc;
}

// ---------------- GEMM2 (mma.sync, BK=128, 4 kc chunks) ----------------
__global__ __launch_bounds__(256) void gemm2_mma(const float* __restrict__ bout,
                                                 float* __restrict__ out) {
    extern __shared__ unsigned short sm[];
    unsigned short* Ah = sm;
    unsigned short* Al = Ah + 128 * KS1;
    unsigned short* Bh = Al + 128 * KS1;
    unsigned short* Bl = Bh + 128 * KS1;
    const int tid = threadIdx.x;
    const int warp = tid >> 5, lane = tid & 31;
    const int wm = warp >> 2, wn = warp & 3;
    const int g = lane >> 2, t = lane & 3;
    const int row0 = blockIdx.x * 128;

    const uint32_t* Ah32 = (const uint32_t*)Ah;
    const uint32_t* Al32 = (const uint32_t*)Al;
    const uint32_t* Bh32 = (const uint32_t*)Bh;
    const uint32_t* Bl32 = (const uint32_t*)Bl;

    float c[4][4][4];
#pragma unroll
    for (int a = 0; a < 4; a++)
#pragma unroll
        for (int bq = 0; bq < 4; bq++)
#pragma unroll
            for (int q = 0; q < 4; q++) c[a][bq][q] = 0.f;

    for (int kc = 0; kc < 4; kc++) {
        int k0 = kc * 128;
        for (int idx = tid; idx < 4096; idx += 256) {
            int r = idx >> 5, k4 = idx & 31;
            int gr = row0 + r;
            int col = k0 + k4 * 4;
            float4 v = make_float4(0.f, 0.f, 0.f, 0.f);
            if (gr < N_NODES) {
                float4 x = *(const float4*)(g_rst + gr * HD + col);
                float4 sc = *(const float4*)(g_scale + col);
                float4 sh = *(const float4*)(g_shift + col);
                v.x = fmaxf(sc.x * x.x + sh.x, 0.f);
                v.y = fmaxf(sc.y * x.y + sh.y, 0.f);
                v.z = fmaxf(sc.z * x.z + sh.z, 0.f);
                v.w = fmaxf(sc.w * x.w + sh.w, 0.f);
            }
            *(uint2*)(Ah + r * KS1 + k4 * 4) = make_uint2(bf2(v.x, v.y), bf2(v.z, v.w));
            *(uint2*)(Al + r * KS1 + k4 * 4) =
                make_uint2(bf2(v.x - bf_round(v.x), v.y - bf_round(v.y)),
                           bf2(v.z - bf_round(v.z), v.w - bf_round(v.w)));
            *(uint2*)(Bh + r * KS1 + k4 * 4) = *(const uint2*)(g_WT2hi + r * 512 + col);
            *(uint2*)(Bl + r * KS1 + k4 * 4) = *(const uint2*)(g_WT2lo + r * 512 + col);
        }
        __syncthreads();
#pragma unroll
        for (int ks = 0; ks < 8; ks++) {
            int kb = ks * 8;
            uint32_t ah[4][4], al[4][4], bh[4][2], bl[4][2];
#pragma unroll
            for (int rb = 0; rb < 4; rb++) {
                int base = (wm * 64 + rb * 16 + g) * KS1_32 + kb + t;
                ah[rb][0] = Ah32[base];             ah[rb][1] = Ah32[base + 8 * KS1_32];
                ah[rb][2] = Ah32[base + 4];         ah[rb][3] = Ah32[base + 8 * KS1_32 + 4];
                al[rb][0] = Al32[base];             al[rb][1] = Al32[base + 8 * KS1_32];
                al[rb][2] = Al32[base + 4];         al[rb][3] = Al32[base + 8 * KS1_32 + 4];
            }
#pragma unroll
            for (int nb = 0; nb < 4; nb++) {
                int base = (wn * 32 + nb * 8 + g) * KS1_32 + kb + t;
                bh[nb][0] = Bh32[base];  bh[nb][1] = Bh32[base + 4];
                bl[nb][0] = Bl32[base];  bl[nb][1] = Bl32[base + 4];
            }
#pragma unroll
            for (int rb = 0; rb < 4; rb++)
#pragma unroll
                for (int nb = 0; nb < 4; nb++) {
                    mma_bf16(c[rb][nb], ah[rb][0], ah[rb][1], ah[rb][2], ah[rb][3],
                             bh[nb][0], bh[nb][1]);
                    mma_bf16(c[rb][nb], al[rb][0], al[rb][1], al[rb][2], al[rb][3],
                             bh[nb][0], bh[nb][1]);
                    mma_bf16(c[rb][nb], ah[rb][0], ah[rb][1], ah[rb][2], ah[rb][3],
                             bl[nb][0], bl[nb][1]);
                }
        }
        __syncthreads();
    }
#pragma unroll
    for (int rb = 0; rb < 4; rb++) {
        int gr0 = row0 + wm * 64 + rb * 16 + g;
#pragma unroll
        for (int nb = 0; nb < 4; nb++) {
            int col = wn * 32 + nb * 8 + 2 * t;
            float* cc = c[rb][nb];
            float2 bv = *(const float2*)(bout + col);
            if (gr0 < N_NODES)
                *(float2*)(out + gr0 * OUTF + col) =
                    make_float2(cc[0] + bv.x, cc[1] + bv.y);
            if (gr0 + 8 < N_NODES)
                *(float2*)(out + (gr0 + 8) * OUTF + col) =
                    make_float2(cc[2] + bv.x, cc[3] + bv.y);
        }
    }
}

// ---------------- launch ----------------
extern "C" void kernel_launch(void* const* d_in, const int* in_sizes, int n_in,
                              void* d_out, int out_size) {
    const float* feat    = (const float*)d_in[0];
    const int*   src     = (const int*)d_in[1];
    const int*   dst     = (const int*)d_in[2];
    const float* Wfc     = (const float*)d_in[3];
    const float* attn_l  = (const float*)d_in[4];
    const float* attn_r  = (const float*)d_in[5];
    const float* Wres    = (const float*)d_in[6];
    const float* biasg   = (const float*)d_in[7];
    const float* gamma   = (const float*)d_in[8];
    const float* beta    = (const float*)d_in[9];
    const float* Wout    = (const float*)d_in[10];
    const float* bout    = (const float*)d_in[11];
    float* out = (float*)d_out;

    cudaFuncSetAttribute(gemm1_mma, cudaFuncAttributeMaxDynamicSharedMemorySize, SMEM_G);
    cudaFuncSetAttribute(gemm2_mma, cudaFuncAttributeMaxDynamicSharedMemorySize, SMEM_G);

    prep_kernel<<<SCAN_NB + 128 + 64 + 8, 256>>>(Wfc, Wres, Wout, attn_l, attn_r);
    elr_kernel<<<(N_NODES + 7) / 8, 256>>>(feat);
    hist_kernel<<<(N_EDGES + 255) / 256, 256>>>(dst);
    scan1_kernel<<<SCAN_NB, 256>>>();
    scan2_kernel<<<1, 1>>>();
    scan3_kernel<<<SCAN_NB, 256>>>();
    scatter_kernel<<<(N_EDGES + 255) / 256, 256>>>(src, dst);
    gemm1_mma<<<dim3(2, NROWB), 256, SMEM_G>>>(feat, biasg);
    agg_kernel<<<(N_NODES + 7) / 8, 256>>>();
    bn_part_kernel<<<BN_BLOCKS, HD>>>();
    bn_final_kernel<<<1, HD>>>(gamma, beta);
    gemm2_mma<<<NROWB, 256, SMEM_G>>>(bout, out);
}

// round 6
// speedup vs baseline: 1.7105x; 1.0389x over previous
#include <cuda_runtime.h>
#include <cuda_bf16.h>
#include <math.h>
#include <stdint.h>

#define N_NODES 30000
#define N_EDGES 480000
#define NHEAD   4
#define HD      512
#define OUTF    128
#define NEG_SLOPE 0.2f
#define BN_EPS  1e-5f
#define BN_BLOCKS 256
#define SCAN_NB 118
#define NROWB   235          // ceil(30000/128)

// ---------------- scratch ----------------
__device__ float g_h[N_NODES * HD];
__device__ float g_rst[N_NODES * HD];
__device__ float g_el[N_NODES * NHEAD];
__device__ float g_er[N_NODES * NHEAD];
__device__ float g_P[8 * 128];
__device__ int   g_deg[N_NODES];
__device__ int   g_cursor[N_NODES];
__device__ int   g_ptr[N_NODES + 1];
__device__ int   g_srcs[N_EDGES];
__device__ int   g_blocksum[SCAN_NB];
__device__ int   g_blockoff[SCAN_NB];
__device__ float g_psum[BN_BLOCKS * HD];
__device__ float g_psq[BN_BLOCKS * HD];
__device__ float g_scale[HD];
__device__ float g_shift[HD];
__device__ unsigned short g_WT1hi[1024 * 128];    // [n][k] for [Wfc|Wres]
__device__ unsigned short g_WT1lo[1024 * 128];
__device__ unsigned short g_WT2hi[128 * 512];     // [n][k] for Wout
__device__ unsigned short g_WT2lo[128 * 512];

// ---------------- helpers ----------------
__device__ __forceinline__ uint32_t bf2(float lo, float hi) {
    uint32_t r;
    asm("cvt.rn.bf16x2.f32 %0, %1, %2;" : "=r"(r) : "f"(hi), "f"(lo));
    return r;
}
__device__ __forceinline__ float bf_round(float x) {
    return __bfloat162float(__float2bfloat16(x));
}
__device__ __forceinline__ unsigned short bf_hi_us(float x) {
    __nv_bfloat16 b = __float2bfloat16(x);
    return *(unsigned short*)&b;
}
__device__ __forceinline__ unsigned short bf_lo_us(float x) {
    __nv_bfloat16 b = __float2bfloat16(x - bf_round(x));
    return *(unsigned short*)&b;
}
__device__ __forceinline__ void mma_bf16(float* c, uint32_t a0, uint32_t a1,
                                         uint32_t a2, uint32_t a3,
                                         uint32_t b0, uint32_t b1) {
    asm volatile(
        "mma.sync.aligned.m16n8k16.row.col.f32.bf16.bf16.f32 "
        "{%0,%1,%2,%3}, {%4,%5,%6,%7}, {%8,%9}, {%0,%1,%2,%3};"
        : "+f"(c[0]), "+f"(c[1]), "+f"(c[2]), "+f"(c[3])
        : "r"(a0), "r"(a1), "r"(a2), "r"(a3), "r"(b0), "r"(b1));
}

// ---------------- fused prep: zero_deg | transpose1 | transpose2 | pvec ------
__global__ __launch_bounds__(256) void prep_kernel(
    const float* __restrict__ Wfc, const float* __restrict__ Wres,
    const float* __restrict__ Wout, const float* __restrict__ attn_l,
    const float* __restrict__ attn_r) {
    int b = blockIdx.x;
    int tid = threadIdx.x;
    if (b < SCAN_NB) {                                  // zero degree
        int i = b * 256 + tid;
        if (i < N_NODES) g_deg[i] = 0;
        return;
    }
    b -= SCAN_NB;
    if (b < 128) {                                      // transpose [Wfc|Wres]
        __shared__ float t[32][33];
        int k0 = (b & 3) * 32;
        int n0 = (b >> 2) * 32;
        int tx = tid & 31, ty = tid >> 5;
        const float* W = (n0 < 512) ? Wfc : Wres;
        int nn0 = (n0 < 512) ? n0 : n0 - 512;
#pragma unroll
        for (int i = 0; i < 32; i += 8)
            t[ty + i][tx] = W[(k0 + ty + i) * 512 + nn0 + tx];
        __syncthreads();
#pragma unroll
        for (int i = 0; i < 32; i += 8) {
            float v = t[tx][ty + i];
            int n = n0 + ty + i, k = k0 + tx;
            g_WT1hi[n * 128 + k] = bf_hi_us(v);
            g_WT1lo[n * 128 + k] = bf_lo_us(v);
        }
        return;
    }
    b -= 128;
    if (b < 64) {                                       // transpose Wout
        __shared__ float t2[32][33];
        int k0 = (b & 15) * 32;
        int n0 = (b >> 4) * 32;
        int tx = tid & 31, ty = tid >> 5;
#pragma unroll
        for (int i = 0; i < 32; i += 8)
            t2[ty + i][tx] = Wout[(k0 + ty + i) * 128 + n0 + tx];
        __syncthreads();
#pragma unroll
        for (int i = 0; i < 32; i += 8) {
            float v = t2[tx][ty + i];
            int n = n0 + ty + i, k = k0 + tx;
            g_WT2hi[n * 512 + k] = bf_hi_us(v);
            g_WT2lo[n * 512 + k] = bf_lo_us(v);
        }
        return;
    }
    b -= 64;                                            // pvec: 8 blocks
    if (tid >= 128) return;
    int h = b & 3;
    const float* av = ((b < 4) ? attn_l : attn_r) + h * 128;
    const float* wr = Wfc + tid * HD + h * 128;
    float s = 0.f;
#pragma unroll
    for (int d4 = 0; d4 < 32; d4++) {
        float4 w = *(const float4*)(wr + d4 * 4);
        float4 a = *(const float4*)(av + d4 * 4);
        s += w.x * a.x + w.y * a.y + w.z * a.z + w.w * a.w;
    }
    g_P[b * 128 + tid] = s;
}

__global__ __launch_bounds__(256) void elr_kernel(const float* __restrict__ feat) {
    __shared__ float Ps[8][128];
    int t = threadIdx.x;
    for (int i = t; i < 1024; i += 256) Ps[i >> 7][i & 127] = g_P[i];
    __syncthreads();
    int n = blockIdx.x * 8 + (t >> 5);
    int lane = t & 31;
    if (n >= N_NODES) return;
    float4 f = *(const float4*)(feat + n * 128 + lane * 4);
    float s[8];
#pragma unroll
    for (int j = 0; j < 8; j++) {
        const float* p = &Ps[j][lane * 4];
        s[j] = f.x * p[0] + f.y * p[1] + f.z * p[2] + f.w * p[3];
    }
#pragma unroll
    for (int o = 16; o; o >>= 1)
#pragma unroll
        for (int j = 0; j < 8; j++) s[j] += __shfl_xor_sync(0xffffffffu, s[j], o);
    if (lane < 4) {
        g_el[n * 4 + lane] = s[lane];
        g_er[n * 4 + lane] = s[lane + 4];
    }
}

// ---------------- CSR build ----------------
__global__ void hist_kernel(const int* __restrict__ dst) {
    int e = blockIdx.x * blockDim.x + threadIdx.x;
    if (e < N_EDGES) atomicAdd(&g_deg[dst[e]], 1);
}

__global__ void scan1_kernel() {
    __shared__ int wsum[8];
    int t = threadIdx.x, b = blockIdx.x;
    int idx = b * 256 + t;
    int lane = t & 31, wid = t >> 5;
    int v = (idx < N_NODES) ? g_deg[idx] : 0;
    int x = v;
#pragma unroll
    for (int o = 1; o < 32; o <<= 1) {
        int y = __shfl_up_sync(0xffffffffu, x, o);
        if (lane >= o) x += y;
    }
    if (lane == 31) wsum[wid] = x;
    __syncthreads();
    if (t == 0) {
        int run = 0;
#pragma unroll
        for (int i = 0; i < 8; i++) { int tmp = wsum[i]; wsum[i] = run; run += tmp; }
        g_blocksum[b] = run;
    }
    __syncthreads();
    int incl = x + wsum[wid];
    if (idx < N_NODES) g_ptr[idx + 1] = incl;
}

__global__ void scan2_kernel() {
    int run = 0;
    for (int i = 0; i < SCAN_NB; i++) {
        int tmp = g_blocksum[i];
        g_blockoff[i] = run;
        run += tmp;
    }
}

__global__ void scan3_kernel() {
    int t = threadIdx.x, b = blockIdx.x;
    int idx = b * 256 + t;
    if (idx >= N_NODES) return;
    int off = g_blockoff[b];
    int incl = g_ptr[idx + 1] + off;
    g_ptr[idx + 1] = incl;
    g_cursor[idx] = incl - g_deg[idx];
    if (idx == 0) g_ptr[0] = 0;
}

__global__ void scatter_kernel(const int* __restrict__ src,
                               const int* __restrict__ dst) {
    int e = blockIdx.x * blockDim.x + threadIdx.x;
    if (e < N_EDGES) {
        int p = atomicAdd(&g_cursor[dst[e]], 1);
        g_srcs[p] = src[e];
    }
}

// ---------------- GEMM1 (mma.sync, full-K smem, 4 n-blocks per CTA) ---------
#define KS1 136
#define KS1_32 68
#define SMEM_G (4 * 128 * KS1 * 2)   // 139264 bytes

__global__ __launch_bounds__(256) void gemm1_mma(const float* __restrict__ feat,
                                                 const float* __restrict__ biasg) {
    extern __shared__ unsigned short sm[];
    unsigned short* Ah = sm;
    unsigned short* Al = Ah + 128 * KS1;
    unsigned short* Bh = Al + 128 * KS1;
    unsigned short* Bl = Bh + 128 * KS1;
    const int tid = threadIdx.x;
    const int warp = tid >> 5, lane = tid & 31;
    const int wm = warp >> 2, wn = warp & 3;
    const int g = lane >> 2, t = lane & 3;
    const int row0 = blockIdx.y * 128;
    const int half = blockIdx.x;

    for (int idx = tid; idx < 4096; idx += 256) {
        int r = idx >> 5, k4 = idx & 31;
        int gr = row0 + r;
        float4 f = make_float4(0.f, 0.f, 0.f, 0.f);
        if (gr < N_NODES) f = *(const float4*)(feat + gr * 128 + k4 * 4);
        *(uint2*)(Ah + r * KS1 + k4 * 4) = make_uint2(bf2(f.x, f.y), bf2(f.z, f.w));
        *(uint2*)(Al + r * KS1 + k4 * 4) =
            make_uint2(bf2(f.x - bf_round(f.x), f.y - bf_round(f.y)),
                       bf2(f.z - bf_round(f.z), f.w - bf_round(f.w)));
    }

    const uint32_t* Ah32 = (const uint32_t*)Ah;
    const uint32_t* Al32 = (const uint32_t*)Al;
    const uint32_t* Bh32 = (const uint32_t*)Bh;
    const uint32_t* Bl32 = (const uint32_t*)Bl;

    for (int i = 0; i < 4; i++) {
        int bx = half * 4 + i;
        for (int idx = tid; idx < 4096; idx += 256) {
            int r = idx >> 5, k4 = idx & 31;
            int n = bx * 128 + r;
            *(uint2*)(Bh + r * KS1 + k4 * 4) = *(const uint2*)(g_WT1hi + n * 128 + k4 * 4);
            *(uint2*)(Bl + r * KS1 + k4 * 4) = *(const uint2*)(g_WT1lo + n * 128 + k4 * 4);
        }
        __syncthreads();

        float c[4][4][4];
#pragma unroll
        for (int a = 0; a < 4; a++)
#pragma unroll
            for (int bq = 0; bq < 4; bq++)
#pragma unroll
                for (int q = 0; q < 4; q++) c[a][bq][q] = 0.f;

#pragma unroll
        for (int ks = 0; ks < 8; ks++) {
            int kb = ks * 8;
            uint32_t ah[4][4], al[4][4], bh[4][2], bl[4][2];
#pragma unroll
            for (int rb = 0; rb < 4; rb++) {
                int base = (wm * 64 + rb * 16 + g) * KS1_32 + kb + t;
                ah[rb][0] = Ah32[base];             ah[rb][1] = Ah32[base + 8 * KS1_32];
                ah[rb][2] = Ah32[base + 4];         ah[rb][3] = Ah32[base + 8 * KS1_32 + 4];
                al[rb][0] = Al32[base];             al[rb][1] = Al32[base + 8 * KS1_32];
                al[rb][2] = Al32[base + 4];         al[rb][3] = Al32[base + 8 * KS1_32 + 4];
            }
#pragma unroll
            for (int nb = 0; nb < 4; nb++) {
                int base = (wn * 32 + nb * 8 + g) * KS1_32 + kb + t;
                bh[nb][0] = Bh32[base];  bh[nb][1] = Bh32[base + 4];
                bl[nb][0] = Bl32[base];  bl[nb][1] = Bl32[base + 4];
            }
#pragma unroll
            for (int rb = 0; rb < 4; rb++)
#pragma unroll
                for (int nb = 0; nb < 4; nb++) {
                    mma_bf16(c[rb][nb], ah[rb][0], ah[rb][1], ah[rb][2], ah[rb][3],
                             bh[nb][0], bh[nb][1]);
                    mma_bf16(c[rb][nb], al[rb][0], al[rb][1], al[rb][2], al[rb][3],
                             bh[nb][0], bh[nb][1]);
                    mma_bf16(c[rb][nb], ah[rb][0], ah[rb][1], ah[rb][2], ah[rb][3],
                             bl[nb][0], bl[nb][1]);
                }
        }
#pragma unroll
        for (int rb = 0; rb < 4; rb++) {
            int gr0 = row0 + wm * 64 + rb * 16 + g;
#pragma unroll
            for (int nb = 0; nb < 4; nb++) {
                int col = bx * 128 + wn * 32 + nb * 8 + 2 * t;
                float* cc = c[rb][nb];
                if (col < 512) {
                    if (gr0 < N_NODES)
                        *(float2*)(g_h + gr0 * HD + col) = make_float2(cc[0], cc[1]);
                    if (gr0 + 8 < N_NODES)
                        *(float2*)(g_h + (gr0 + 8) * HD + col) = make_float2(cc[2], cc[3]);
                } else {
                    int cb = col - 512;
                    float2 bv = *(const float2*)(biasg + cb);
                    if (gr0 < N_NODES)
                        *(float2*)(g_rst + gr0 * HD + cb) =
                            make_float2(cc[0] + bv.x, cc[1] + bv.y);
                    if (gr0 + 8 < N_NODES)
                        *(float2*)(g_rst + (gr0 + 8) * HD + cb) =
                            make_float2(cc[2] + bv.x, cc[3] + bv.y);
                }
            }
        }
        __syncthreads();
    }
}

// ---------------- aggregation (unchanged, validated) ----------------
__global__ __launch_bounds__(256) void agg_kernel() {
    int v = blockIdx.x * 8 + (threadIdx.x >> 5);
    int lane = threadIdx.x & 31;
    if (v >= N_NODES) return;
    int start = g_ptr[v], end = g_ptr[v + 1];
    if (start == end) return;
    float4 er = *(const float4*)(g_er + v * 4);

    float4 a0 = make_float4(0.f, 0.f, 0.f, 0.f);
    float4 a1 = a0, a2 = a0, a3 = a0;
    float d0 = 0.f, d1 = 0.f, d2 = 0.f, d3 = 0.f;

    for (int j = start; j < end; j++) {
        int s = g_srcs[j];
        float4 el = *(const float4*)(g_el + s * 4);
        const float* hp = g_h + s * HD + lane * 4;
        float4 h0 = *(const float4*)(hp);
        float4 h1 = *(const float4*)(hp + 128);
        float4 h2 = *(const float4*)(hp + 256);
        float4 h3 = *(const float4*)(hp + 384);
        float e0 = el.x + er.x; e0 = (e0 > 0.f) ? e0 : NEG_SLOPE * e0;
        float e1 = el.y + er.y; e1 = (e1 > 0.f) ? e1 : NEG_SLOPE * e1;
        float e2 = el.z + er.z; e2 = (e2 > 0.f) ? e2 : NEG_SLOPE * e2;
        float e3 = el.w + er.w; e3 = (e3 > 0.f) ? e3 : NEG_SLOPE * e3;
        float w0 = __expf(e0), w1 = __expf(e1), w2 = __expf(e2), w3 = __expf(e3);
        d0 += w0; d1 += w1; d2 += w2; d3 += w3;
        a0.x += w0 * h0.x; a0.y += w0 * h0.y; a0.z += w0 * h0.z; a0.w += w0 * h0.w;
        a1.x += w1 * h1.x; a1.y += w1 * h1.y; a1.z += w1 * h1.z; a1.w += w1 * h1.w;
        a2.x += w2 * h2.x; a2.y += w2 * h2.y; a2.z += w2 * h2.z; a2.w += w2 * h2.w;
        a3.x += w3 * h3.x; a3.y += w3 * h3.y; a3.z += w3 * h3.z; a3.w += w3 * h3.w;
    }
    float i0 = 1.f / d0, i1 = 1.f / d1, i2 = 1.f / d2, i3 = 1.f / d3;
    float* o = g_rst + v * HD + lane * 4;
    float4 c0 = *(float4*)(o);
    float4 c1 = *(float4*)(o + 128);
    float4 c2 = *(float4*)(o + 256);
    float4 c3 = *(float4*)(o + 384);
    c0.x += a0.x * i0; c0.y += a0.y * i0; c0.z += a0.z * i0; c0.w += a0.w * i0;
    c1.x += a1.x * i1; c1.y += a1.y * i1; c1.z += a1.z * i1; c1.w += a1.w * i1;
    c2.x += a2.x * i2; c2.y += a2.y * i2; c2.z += a2.z * i2; c2.w += a2.w * i2;
    c3.x += a3.x * i3; c3.y += a3.y * i3; c3.z += a3.z * i3; c3.w += a3.w * i3;
    *(float4*)(o)       = c0;
    *(float4*)(o + 128) = c1;
    *(float4*)(o + 256) = c2;
    *(float4*)(o + 384) = c3;
}

// ---------------- BatchNorm stats ----------------
__global__ void bn_part_kernel() {
    int c = threadIdx.x;
    float s = 0.f, q = 0.f;
    for (int r = blockIdx.x; r < N_NODES; r += gridDim.x) {
        float x = g_rst[r * HD + c];
        s += x;
        q += x * x;
    }
    g_psum[blockIdx.x * HD + c] = s;
    g_psq[blockIdx.x * HD + c] = q;
}

__global__ void bn_final_kernel(const float* __restrict__ gamma,
                                const float* __restrict__ beta) {
    int c = threadIdx.x;
    float s = 0.f, q = 0.f;
    for (int b = 0; b < BN_BLOCKS; b++) {
        s += g_psum[b * HD + c];
        q += g_psq[b * HD + c];
    }
    float mu = s / (float)N_NODES;
    float var = q / (float)N_NODES - mu * mu;
    float rstd = rsqrtf(var + BN_EPS);
    float sc = gamma[c] * rstd;
    g_scale[c] = sc;
    g_shift[c] = beta[c] - mu * sc;
}

// ---------------- GEMM2 (mma.sync, BK=128, 4 kc chunks) ----------------
__global__ __launch_bounds__(256) void gemm2_mma(const float* __restrict__ bout,
                                                 float* __restrict__ out) {
    extern __shared__ unsigned short sm[];
    unsigned short* Ah = sm;
    unsigned short* Al = Ah + 128 * KS1;
    unsigned short* Bh = Al + 128 * KS1;
    unsigned short* Bl = Bh + 128 * KS1;
    const int tid = threadIdx.x;
    const int warp = tid >> 5, lane = tid & 31;
    const int wm = warp >> 2, wn = warp & 3;
    const int g = lane >> 2, t = lane & 3;
    const int row0 = blockIdx.x * 128;

    const uint32_t* Ah32 = (const uint32_t*)Ah;
    const uint32_t* Al32 = (const uint32_t*)Al;
    const uint32_t* Bh32 = (const uint32_t*)Bh;
    const uint32_t* Bl32 = (const uint32_t*)Bl;

    float c[4][4][4];
#pragma unroll
    for (int a = 0; a < 4; a++)
#pragma unroll
        for (int bq = 0; bq < 4; bq++)
#pragma unroll
            for (int q = 0; q < 4; q++) c[a][bq][q] = 0.f;

    for (int kc = 0; kc < 4; kc++) {
        int k0 = kc * 128;
        for (int idx = tid; idx < 4096; idx += 256) {
            int r = idx >> 5, k4 = idx & 31;
            int gr = row0 + r;
            int col = k0 + k4 * 4;
            float4 v = make_float4(0.f, 0.f, 0.f, 0.f);
            if (gr < N_NODES) {
                float4 x = *(const float4*)(g_rst + gr * HD + col);
                float4 sc = *(const float4*)(g_scale + col);
                float4 sh = *(const float4*)(g_shift + col);
                v.x = fmaxf(sc.x * x.x + sh.x, 0.f);
                v.y = fmaxf(sc.y * x.y + sh.y, 0.f);
                v.z = fmaxf(sc.z * x.z + sh.z, 0.f);
                v.w = fmaxf(sc.w * x.w + sh.w, 0.f);
            }
            *(uint2*)(Ah + r * KS1 + k4 * 4) = make_uint2(bf2(v.x, v.y), bf2(v.z, v.w));
            *(uint2*)(Al + r * KS1 + k4 * 4) =
                make_uint2(bf2(v.x - bf_round(v.x), v.y - bf_round(v.y)),
                           bf2(v.z - bf_round(v.z), v.w - bf_round(v.w)));
            *(uint2*)(Bh + r * KS1 + k4 * 4) = *(const uint2*)(g_WT2hi + r * 512 + col);
            *(uint2*)(Bl + r * KS1 + k4 * 4) = *(const uint2*)(g_WT2lo + r * 512 + col);
        }
        __syncthreads();
#pragma unroll
        for (int ks = 0; ks < 8; ks++) {
            int kb = ks * 8;
            uint32_t ah[4][4], al[4][4], bh[4][2], bl[4][2];
#pragma unroll
            for (int rb = 0; rb < 4; rb++) {
                int base = (wm * 64 + rb * 16 + g) * KS1_32 + kb + t;
                ah[rb][0] = Ah32[base];             ah[rb][1] = Ah32[base + 8 * KS1_32];
                ah[rb][2] = Ah32[base + 4];         ah[rb][3] = Ah32[base + 8 * KS1_32 + 4];
                al[rb][0] = Al32[base];             al[rb][1] = Al32[base + 8 * KS1_32];
                al[rb][2] = Al32[base + 4];         al[rb][3] = Al32[base + 8 * KS1_32 + 4];
            }
#pragma unroll
            for (int nb = 0; nb < 4; nb++) {
                int base = (wn * 32 + nb * 8 + g) * KS1_32 + kb + t;
                bh[nb][0] = Bh32[base];  bh[nb][1] = Bh32[base + 4];
                bl[nb][0] = Bl32[base];  bl[nb][1] = Bl32[base + 4];
            }
#pragma unroll
            for (int rb = 0; rb < 4; rb++)
#pragma unroll
                for (int nb = 0; nb < 4; nb++) {
                    mma_bf16(c[rb][nb], ah[rb][0], ah[rb][1], ah[rb][2], ah[rb][3],
                             bh[nb][0], bh[nb][1]);
                    mma_bf16(c[rb][nb], al[rb][0], al[rb][1], al[rb][2], al[rb][3],
                             bh[nb][0], bh[nb][1]);
                    mma_bf16(c[rb][nb], ah[rb][0], ah[rb][1], ah[rb][2], ah[rb][3],
                             bl[nb][0], bl[nb][1]);
                }
        }
        __syncthreads();
    }
#pragma unroll
    for (int rb = 0; rb < 4; rb++) {
        int gr0 = row0 + wm * 64 + rb * 16 + g;
#pragma unroll
        for (int nb = 0; nb < 4; nb++) {
            int col = wn * 32 + nb * 8 + 2 * t;
            float* cc = c[rb][nb];
            float2 bv = *(const float2*)(bout + col);
            if (gr0 < N_NODES)
                *(float2*)(out + gr0 * OUTF + col) =
                    make_float2(cc[0] + bv.x, cc[1] + bv.y);
            if (gr0 + 8 < N_NODES)
                *(float2*)(out + (gr0 + 8) * OUTF + col) =
                    make_float2(cc[2] + bv.x, cc[3] + bv.y);
        }
    }
}

// ---------------- launch (fork/join overlap) ----------------
extern "C" void kernel_launch(void* const* d_in, const int* in_sizes, int n_in,
                              void* d_out, int out_size) {
    const float* feat    = (const float*)d_in[0];
    const int*   src     = (const int*)d_in[1];
    const int*   dst     = (const int*)d_in[2];
    const float* Wfc     = (const float*)d_in[3];
    const float* attn_l  = (const float*)d_in[4];
    const float* attn_r  = (const float*)d_in[5];
    const float* Wres    = (const float*)d_in[6];
    const float* biasg   = (const float*)d_in[7];
    const float* gamma   = (const float*)d_in[8];
    const float* beta    = (const float*)d_in[9];
    const float* Wout    = (const float*)d_in[10];
    const float* bout    = (const float*)d_in[11];
    float* out = (float*)d_out;

    // One-time resource setup (runs on the uncaptured correctness call;
    // handles are reused during graph capture — documented fork/join pattern).
    static cudaStream_t sB = nullptr;
    static cudaEvent_t evRoot = nullptr, evCsr = nullptr;
    if (sB == nullptr) {
        cudaStreamCreateWithFlags(&sB, cudaStreamNonBlocking);
        cudaEventCreateWithFlags(&evRoot, cudaEventDisableTiming);
        cudaEventCreateWithFlags(&evCsr, cudaEventDisableTiming);
        cudaFuncSetAttribute(gemm1_mma, cudaFuncAttributeMaxDynamicSharedMemorySize, SMEM_G);
        cudaFuncSetAttribute(gemm2_mma, cudaFuncAttributeMaxDynamicSharedMemorySize, SMEM_G);
    }

    // main stream: weights prep (also zeroes g_deg)
    prep_kernel<<<SCAN_NB + 128 + 64 + 8, 256>>>(Wfc, Wres, Wout, attn_l, attn_r);
    cudaEventRecord(evRoot, 0);

    // fork: CSR build on side stream (independent of GEMM path)
    cudaStreamWaitEvent(sB, evRoot, 0);
    hist_kernel<<<(N_EDGES + 255) / 256, 256, 0, sB>>>(dst);
    scan1_kernel<<<SCAN_NB, 256, 0, sB>>>();
    scan2_kernel<<<1, 1, 0, sB>>>();
    scan3_kernel<<<SCAN_NB, 256, 0, sB>>>();
    scatter_kernel<<<(N_EDGES + 255) / 256, 256, 0, sB>>>(src, dst);
    cudaEventRecord(evCsr, sB);

    // main stream: attention logits + projection GEMM (overlaps CSR chain)
    elr_kernel<<<(N_NODES + 7) / 8, 256>>>(feat);
    gemm1_mma<<<dim3(2, NROWB), 256, SMEM_G>>>(feat, biasg);

    // join: aggregation needs both paths
    cudaStreamWaitEvent(0, evCsr, 0);
    agg_kernel<<<(N_NODES + 7) / 8, 256>>>();
    bn_part_kernel<<<BN_BLOCKS, HD>>>();
    bn_final_kernel<<<1, HD>>>(gamma, beta);
    gemm2_mma<<<NROWB, 256, SMEM_G>>>(bout, out);
}

// round 8
// speedup vs baseline: 1.7125x; 1.0012x over previous
#include <cuda_runtime.h>
#include <cuda_bf16.h>
#include <cuda_fp16.h>
#include <math.h>
#include <stdint.h>

#define N_NODES 30000
#define N_EDGES 480000
#define NHEAD   4
#define HD      512
#define OUTF    128
#define NEG_SLOPE 0.2f
#define BN_EPS  1e-5f
#define BN_BLOCKS 256
#define SCAN_NB 118
#define NROWB   235          // ceil(30000/128)

// ---------------- scratch ----------------
__device__ unsigned short g_h16[N_NODES * HD];   // fp16 projected feats (agg only)
__device__ float g_rst[N_NODES * HD];
__device__ float g_el[N_NODES * NHEAD];
__device__ float g_er[N_NODES * NHEAD];
__device__ float g_P[8 * 128];
__device__ int   g_deg[N_NODES];
__device__ int   g_cursor[N_NODES];
__device__ int   g_ptr[N_NODES + 1];
__device__ int   g_srcs[N_EDGES];
__device__ int   g_blocksum[SCAN_NB];
__device__ int   g_blockoff[SCAN_NB];
__device__ float g_psum[BN_BLOCKS * HD];
__device__ float g_psq[BN_BLOCKS * HD];
__device__ float g_scale[HD];
__device__ float g_shift[HD];
__device__ unsigned short g_WT1hi[1024 * 128];    // [n][k] for [Wfc|Wres]
__device__ unsigned short g_WT1lo[1024 * 128];
__device__ unsigned short g_WT2hi[128 * 512];     // [n][k] for Wout
__device__ unsigned short g_WT2lo[128 * 512];

// ---------------- helpers ----------------
__device__ __forceinline__ uint32_t bf2(float lo, float hi) {
    uint32_t r;
    asm("cvt.rn.bf16x2.f32 %0, %1, %2;" : "=r"(r) : "f"(hi), "f"(lo));
    return r;
}
__device__ __forceinline__ float bf_round(float x) {
    return __bfloat162float(__float2bfloat16(x));
}
__device__ __forceinline__ unsigned short bf_hi_us(float x) {
    __nv_bfloat16 b = __float2bfloat16(x);
    return *(unsigned short*)&b;
}
__device__ __forceinline__ unsigned short bf_lo_us(float x) {
    __nv_bfloat16 b = __float2bfloat16(x - bf_round(x));
    return *(unsigned short*)&b;
}
__device__ __forceinline__ uint32_t f2h2(float lo, float hi) {
    __half2 h = __floats2half2_rn(lo, hi);
    return *(uint32_t*)&h;
}
__device__ __forceinline__ void mma_bf16(float* c, uint32_t a0, uint32_t a1,
                                         uint32_t a2, uint32_t a3,
                                         uint32_t b0, uint32_t b1) {
    asm volatile(
        "mma.sync.aligned.m16n8k16.row.col.f32.bf16.bf16.f32 "
        "{%0,%1,%2,%3}, {%4,%5,%6,%7}, {%8,%9}, {%0,%1,%2,%3};"
        : "+f"(c[0]), "+f"(c[1]), "+f"(c[2]), "+f"(c[3])
        : "r"(a0), "r"(a1), "r"(a2), "r"(a3), "r"(b0), "r"(b1));
}
__device__ __forceinline__ float2 h2f(uint32_t u) {
    return __half22float2(*(__half2*)&u);
}

// ---------------- fused prep: zero_deg | transpose1 | transpose2 | pvec ------
__global__ __launch_bounds__(256) void prep_kernel(
    const float* __restrict__ Wfc, const float* __restrict__ Wres,
    const float* __restrict__ Wout, const float* __restrict__ attn_l,
    const float* __restrict__ attn_r) {
    int b = blockIdx.x;
    int tid = threadIdx.x;
    if (b < SCAN_NB) {
        int i = b * 256 + tid;
        if (i < N_NODES) g_deg[i] = 0;
        return;
    }
    b -= SCAN_NB;
    if (b < 128) {
        __shared__ float t[32][33];
        int k0 = (b & 3) * 32;
        int n0 = (b >> 2) * 32;
        int tx = tid & 31, ty = tid >> 5;
        const float* W = (n0 < 512) ? Wfc : Wres;
        int nn0 = (n0 < 512) ? n0 : n0 - 512;
#pragma unroll
        for (int i = 0; i < 32; i += 8)
            t[ty + i][tx] = W[(k0 + ty + i) * 512 + nn0 + tx];
        __syncthreads();
#pragma unroll
        for (int i = 0; i < 32; i += 8) {
            float v = t[tx][ty + i];
            int n = n0 + ty + i, k = k0 + tx;
            g_WT1hi[n * 128 + k] = bf_hi_us(v);
            g_WT1lo[n * 128 + k] = bf_lo_us(v);
        }
        return;
    }
    b -= 128;
    if (b < 64) {
        __shared__ float t2[32][33];
        int k0 = (b & 15) * 32;
        int n0 = (b >> 4) * 32;
        int tx = tid & 31, ty = tid >> 5;
#pragma unroll
        for (int i = 0; i < 32; i += 8)
            t2[ty + i][tx] = Wout[(k0 + ty + i) * 128 + n0 + tx];
        __syncthreads();
#pragma unroll
        for (int i = 0; i < 32; i += 8) {
            float v = t2[tx][ty + i];
            int n = n0 + ty + i, k = k0 + tx;
            g_WT2hi[n * 512 + k] = bf_hi_us(v);
            g_WT2lo[n * 512 + k] = bf_lo_us(v);
        }
        return;
    }
    b -= 64;
    if (tid >= 128) return;
    int h = b & 3;
    const float* av = ((b < 4) ? attn_l : attn_r) + h * 128;
    const float* wr = Wfc + tid * HD + h * 128;
    float s = 0.f;
#pragma unroll
    for (int d4 = 0; d4 < 32; d4++) {
        float4 w = *(const float4*)(wr + d4 * 4);
        float4 a = *(const float4*)(av + d4 * 4);
        s += w.x * a.x + w.y * a.y + w.z * a.z + w.w * a.w;
    }
    g_P[b * 128 + tid] = s;
}

__global__ __launch_bounds__(256) void elr_kernel(const float* __restrict__ feat) {
    __shared__ float Ps[8][128];
    int t = threadIdx.x;
    for (int i = t; i < 1024; i += 256) Ps[i >> 7][i & 127] = g_P[i];
    __syncthreads();
    int n = blockIdx.x * 8 + (t >> 5);
    int lane = t & 31;
    if (n >= N_NODES) return;
    float4 f = *(const float4*)(feat + n * 128 + lane * 4);
    float s[8];
#pragma unroll
    for (int j = 0; j < 8; j++) {
        const float* p = &Ps[j][lane * 4];
        s[j] = f.x * p[0] + f.y * p[1] + f.z * p[2] + f.w * p[3];
    }
#pragma unroll
    for (int o = 16; o; o >>= 1)
#pragma unroll
        for (int j = 0; j < 8; j++) s[j] += __shfl_xor_sync(0xffffffffu, s[j], o);
    if (lane < 4) {
        g_el[n * 4 + lane] = s[lane];
        g_er[n * 4 + lane] = s[lane + 4];
    }
}

// ---------------- CSR build ----------------
__global__ void hist_kernel(const int* __restrict__ dst) {
    int e = blockIdx.x * blockDim.x + threadIdx.x;
    if (e < N_EDGES) atomicAdd(&g_deg[dst[e]], 1);
}

__global__ void scan1_kernel() {
    __shared__ int wsum[8];
    int t = threadIdx.x, b = blockIdx.x;
    int idx = b * 256 + t;
    int lane = t & 31, wid = t >> 5;
    int v = (idx < N_NODES) ? g_deg[idx] : 0;
    int x = v;
#pragma unroll
    for (int o = 1; o < 32; o <<= 1) {
        int y = __shfl_up_sync(0xffffffffu, x, o);
        if (lane >= o) x += y;
    }
    if (lane == 31) wsum[wid] = x;
    __syncthreads();
    if (t == 0) {
        int run = 0;
#pragma unroll
        for (int i = 0; i < 8; i++) { int tmp = wsum[i]; wsum[i] = run; run += tmp; }
        g_blocksum[b] = run;
    }
    __syncthreads();
    int incl = x + wsum[wid];
    if (idx < N_NODES) g_ptr[idx + 1] = incl;
}

// 128-thread warp-scan over SCAN_NB block sums
__global__ void scan2_kernel() {
    __shared__ int ws[4];
    int t = threadIdx.x;
    int lane = t & 31, w = t >> 5;
    int v = (t < SCAN_NB) ? g_blocksum[t] : 0;
    int x = v;
#pragma unroll
    for (int o = 1; o < 32; o <<= 1) {
        int y = __shfl_up_sync(0xffffffffu, x, o);
        if (lane >= o) x += y;
    }
    if (lane == 31) ws[w] = x;
    __syncthreads();
    if (t == 0) {
        int run = 0;
#pragma unroll
        for (int i = 0; i < 4; i++) { int tmp = ws[i]; ws[i] = run; run += tmp; }
    }
    __syncthreads();
    if (t < SCAN_NB) g_blockoff[t] = x + ws[w] - v;   // exclusive
}

__global__ void scan3_kernel() {
    int t = threadIdx.x, b = blockIdx.x;
    int idx = b * 256 + t;
    if (idx >= N_NODES) return;
    int off = g_blockoff[b];
    int incl = g_ptr[idx + 1] + off;
    g_ptr[idx + 1] = incl;
    g_cursor[idx] = incl - g_deg[idx];
    if (idx == 0) g_ptr[0] = 0;
}

__global__ void scatter_kernel(const int* __restrict__ src,
                               const int* __restrict__ dst) {
    int e = blockIdx.x * blockDim.x + threadIdx.x;
    if (e < N_EDGES) {
        int p = atomicAdd(&g_cursor[dst[e]], 1);
        g_srcs[p] = src[e];
    }
}

// ---------------- GEMM1 (mma.sync, full-K smem, 4 n-blocks per CTA) ---------
#define KS1 136
#define KS1_32 68
#define SMEM_G (4 * 128 * KS1 * 2)   // 139264 bytes

__global__ __launch_bounds__(256) void gemm1_mma(const float* __restrict__ feat,
                                                 const float* __restrict__ biasg) {
    extern __shared__ unsigned short sm[];
    unsigned short* Ah = sm;
    unsigned short* Al = Ah + 128 * KS1;
    unsigned short* Bh = Al + 128 * KS1;
    unsigned short* Bl = Bh + 128 * KS1;
    const int tid = threadIdx.x;
    const int warp = tid >> 5, lane = tid & 31;
    const int wm = warp >> 2, wn = warp & 3;
    const int g = lane >> 2, t = lane & 3;
    const int row0 = blockIdx.y * 128;
    const int half = blockIdx.x;

    for (int idx = tid; idx < 4096; idx += 256) {
        int r = idx >> 5, k4 = idx & 31;
        int gr = row0 + r;
        float4 f = make_float4(0.f, 0.f, 0.f, 0.f);
        if (gr < N_NODES) f = *(const float4*)(feat + gr * 128 + k4 * 4);
        *(uint2*)(Ah + r * KS1 + k4 * 4) = make_uint2(bf2(f.x, f.y), bf2(f.z, f.w));
        *(uint2*)(Al + r * KS1 + k4 * 4) =
            make_uint2(bf2(f.x - bf_round(f.x), f.y - bf_round(f.y)),
                       bf2(f.z - bf_round(f.z), f.w - bf_round(f.w)));
    }

    const uint32_t* Ah32 = (const uint32_t*)Ah;
    const uint32_t* Al32 = (const uint32_t*)Al;
    const uint32_t* Bh32 = (const uint32_t*)Bh;
    const uint32_t* Bl32 = (const uint32_t*)Bl;

    for (int i = 0; i < 4; i++) {
        int bx = half * 4 + i;
        for (int idx = tid; idx < 4096; idx += 256) {
            int r = idx >> 5, k4 = idx & 31;
            int n = bx * 128 + r;
            *(uint2*)(Bh + r * KS1 + k4 * 4) = *(const uint2*)(g_WT1hi + n * 128 + k4 * 4);
            *(uint2*)(Bl + r * KS1 + k4 * 4) = *(const uint2*)(g_WT1lo + n * 128 + k4 * 4);
        }
        __syncthreads();

        float c[4][4][4];
#pragma unroll
        for (int a = 0; a < 4; a++)
#pragma unroll
            for (int bq = 0; bq < 4; bq++)
#pragma unroll
                for (int q = 0; q < 4; q++) c[a][bq][q] = 0.f;

#pragma unroll
        for (int ks = 0; ks < 8; ks++) {
            int kb = ks * 8;
            uint32_t ah[4][4], al[4][4], bh[4][2], bl[4][2];
#pragma unroll
            for (int rb = 0; rb < 4; rb++) {
                int base = (wm * 64 + rb * 16 + g) * KS1_32 + kb + t;
                ah[rb][0] = Ah32[base];             ah[rb][1] = Ah32[base + 8 * KS1_32];
                ah[rb][2] = Ah32[base + 4];         ah[rb][3] = Ah32[base + 8 * KS1_32 + 4];
                al[rb][0] = Al32[base];             al[rb][1] = Al32[base + 8 * KS1_32];
                al[rb][2] = Al32[base + 4];         al[rb][3] = Al32[base + 8 * KS1_32 + 4];
            }
#pragma unroll
            for (int nb = 0; nb < 4; nb++) {
                int base = (wn * 32 + nb * 8 + g) * KS1_32 + kb + t;
                bh[nb][0] = Bh32[base];  bh[nb][1] = Bh32[base + 4];
                bl[nb][0] = Bl32[base];  bl[nb][1] = Bl32[base + 4];
            }
#pragma unroll
            for (int rb = 0; rb < 4; rb++)
#pragma unroll
                for (int nb = 0; nb < 4; nb++) {
                    mma_bf16(c[rb][nb], ah[rb][0], ah[rb][1], ah[rb][2], ah[rb][3],
                             bh[nb][0], bh[nb][1]);
                    mma_bf16(c[rb][nb], al[rb][0], al[rb][1], al[rb][2], al[rb][3],
                             bh[nb][0], bh[nb][1]);
                    mma_bf16(c[rb][nb], ah[rb][0], ah[rb][1], ah[rb][2], ah[rb][3],
                             bl[nb][0], bl[nb][1]);
                }
        }
#pragma unroll
        for (int rb = 0; rb < 4; rb++) {
            int gr0 = row0 + wm * 64 + rb * 16 + g;
#pragma unroll
            for (int nb = 0; nb < 4; nb++) {
                int col = bx * 128 + wn * 32 + nb * 8 + 2 * t;
                float* cc = c[rb][nb];
                if (col < 512) {
                    if (gr0 < N_NODES)
                        *(uint32_t*)(g_h16 + gr0 * HD + col) = f2h2(cc[0], cc[1]);
                    if (gr0 + 8 < N_NODES)
                        *(uint32_t*)(g_h16 + (gr0 + 8) * HD + col) = f2h2(cc[2], cc[3]);
                } else {
                    int cb = col - 512;
                    float2 bv = *(const float2*)(biasg + cb);
                    if (gr0 < N_NODES)
                        *(float2*)(g_rst + gr0 * HD + cb) =
                            make_float2(cc[0] + bv.x, cc[1] + bv.y);
                    if (gr0 + 8 < N_NODES)
                        *(float2*)(g_rst + (gr0 + 8) * HD + cb) =
                            make_float2(cc[2] + bv.x, cc[3] + bv.y);
                }
            }
        }
        __syncthreads();
    }
}

// ---------------- aggregation: 4 nodes per warp, fp16 gather, prefetch ------
__global__ __launch_bounds__(256) void agg_kernel() {
    int wg = blockIdx.x * 8 + (threadIdx.x >> 5);
    int lane = threadIdx.x & 31;
#pragma unroll 1
    for (int q = 0; q < 4; q++) {
        int v = wg * 4 + q;
        if (v >= N_NODES) return;
        int start = g_ptr[v], end = g_ptr[v + 1];
        if (start == end) continue;   // keep residual+bias only
        float4 er = *(const float4*)(g_er + v * 4);

        float4 a0 = make_float4(0.f, 0.f, 0.f, 0.f);
        float4 a1 = a0, a2 = a0, a3 = a0;
        float d0 = 0.f, d1 = 0.f, d2 = 0.f, d3 = 0.f;

        int s = g_srcs[start];
        float4 el = *(const float4*)(g_el + s * 4);
        for (int j = start; j < end; j++) {
            int jn = (j + 1 < end) ? j + 1 : j;
            int s2 = g_srcs[jn];
            float4 el2 = *(const float4*)(g_el + s2 * 4);

            const unsigned short* hp = g_h16 + s * HD + lane * 4;
            uint2 q0 = *(const uint2*)(hp);
            uint2 q1 = *(const uint2*)(hp + 128);
            uint2 q2 = *(const uint2*)(hp + 256);
            uint2 q3 = *(const uint2*)(hp + 384);

            float e0 = el.x + er.x; e0 = (e0 > 0.f) ? e0 : NEG_SLOPE * e0;
            float e1 = el.y + er.y; e1 = (e1 > 0.f) ? e1 : NEG_SLOPE * e1;
            float e2 = el.z + er.z; e2 = (e2 > 0.f) ? e2 : NEG_SLOPE * e2;
            float e3 = el.w + er.w; e3 = (e3 > 0.f) ? e3 : NEG_SLOPE * e3;
            float w0 = __expf(e0), w1 = __expf(e1), w2 = __expf(e2), w3 = __expf(e3);
            d0 += w0; d1 += w1; d2 += w2; d3 += w3;

            float2 p;
            p = h2f(q0.x); a0.x += w0 * p.x; a0.y += w0 * p.y;
            p = h2f(q0.y); a0.z += w0 * p.x; a0.w += w0 * p.y;
            p = h2f(q1.x); a1.x += w1 * p.x; a1.y += w1 * p.y;
            p = h2f(q1.y); a1.z += w1 * p.x; a1.w += w1 * p.y;
            p = h2f(q2.x); a2.x += w2 * p.x; a2.y += w2 * p.y;
            p = h2f(q2.y); a2.z += w2 * p.x; a2.w += w2 * p.y;
            p = h2f(q3.x); a3.x += w3 * p.x; a3.y += w3 * p.y;
            p = h2f(q3.y); a3.z += w3 * p.x; a3.w += w3 * p.y;

            s = s2; el = el2;
        }
        float i0 = 1.f / d0, i1 = 1.f / d1, i2 = 1.f / d2, i3 = 1.f / d3;
        float* o = g_rst + v * HD + lane * 4;
        float4 c0 = *(float4*)(o);
        float4 c1 = *(float4*)(o + 128);
        float4 c2 = *(float4*)(o + 256);
        float4 c3 = *(float4*)(o + 384);
        c0.x += a0.x * i0; c0.y += a0.y * i0; c0.z += a0.z * i0; c0.w += a0.w * i0;
        c1.x += a1.x * i1; c1.y += a1.y * i1; c1.z += a1.z * i1; c1.w += a1.w * i1;
        c2.x += a2.x * i2; c2.y += a2.y * i2; c2.z += a2.z * i2; c2.w += a2.w * i2;
        c3.x += a3.x * i3; c3.y += a3.y * i3; c3.z += a3.z * i3; c3.w += a3.w * i3;
        *(float4*)(o)       = c0;
        *(float4*)(o + 128) = c1;
        *(float4*)(o + 256) = c2;
        *(float4*)(o + 384) = c3;
    }
}

// ---------------- BatchNorm stats ----------------
__global__ void bn_part_kernel() {
    int c = threadIdx.x;
    float s = 0.f, q = 0.f;
    for (int r = blockIdx.x; r < N_NODES; r += gridDim.x) {
        float x = g_rst[r * HD + c];
        s += x;
        q += x * x;
    }
    g_psum[blockIdx.x * HD + c] = s;
    g_psq[blockIdx.x * HD + c] = q;
}

__global__ void bn_final_kernel(const float* __restrict__ gamma,
                                const float* __restrict__ beta) {
    int c = threadIdx.x;
    float s = 0.f, q = 0.f;
    for (int b = 0; b < BN_BLOCKS; b++) {
        s += g_psum[b * HD + c];
        q += g_psq[b * HD + c];
    }
    float mu = s / (float)N_NODES;
    float var = q / (float)N_NODES - mu * mu;
    float rstd = rsqrtf(var + BN_EPS);
    float sc = gamma[c] * rstd;
    g_scale[c] = sc;
    g_shift[c] = beta[c] - mu * sc;
}

// ---------------- GEMM2 (mma.sync, BK=128, 4 kc chunks) ----------------
__global__ __launch_bounds__(256) void gemm2_mma(const float* __restrict__ bout,
                                                 float* __restrict__ out) {
    extern __shared__ unsigned short sm[];
    unsigned short* Ah = sm;
    unsigned short* Al = Ah + 128 * KS1;
    unsigned short* Bh = Al + 128 * KS1;
    unsigned short* Bl = Bh + 128 * KS1;
    const int tid = threadIdx.x;
    const int warp = tid >> 5, lane = tid & 31;
    const int wm = warp >> 2, wn = warp & 3;
    const int g = lane >> 2, t = lane & 3;
    const int row0 = blockIdx.x * 128;

    const uint32_t* Ah32 = (const uint32_t*)Ah;
    const uint32_t* Al32 = (const uint32_t*)Al;
    const uint32_t* Bh32 = (const uint32_t*)Bh;
    const uint32_t* Bl32 = (const uint32_t*)Bl;

    float c[4][4][4];
#pragma unroll
    for (int a = 0; a < 4; a++)
#pragma unroll
        for (int bq = 0; bq < 4; bq++)
#pragma unroll
            for (int q = 0; q < 4; q++) c[a][bq][q] = 0.f;

    for (int kc = 0; kc < 4; kc++) {
        int k0 = kc * 128;
        for (int idx = tid; idx < 4096; idx += 256) {
            int r = idx >> 5, k4 = idx & 31;
            int gr = row0 + r;
            int col = k0 + k4 * 4;
            float4 v = make_float4(0.f, 0.f, 0.f, 0.f);
            if (gr < N_NODES) {
                float4 x = *(const float4*)(g_rst + gr * HD + col);
                float4 sc = *(const float4*)(g_scale + col);
                float4 sh = *(const float4*)(g_shift + col);
                v.x = fmaxf(sc.x * x.x + sh.x, 0.f);
                v.y = fmaxf(sc.y * x.y + sh.y, 0.f);
                v.z = fmaxf(sc.z * x.z + sh.z, 0.f);
                v.w = fmaxf(sc.w * x.w + sh.w, 0.f);
            }
            *(uint2*)(Ah + r * KS1 + k4 * 4) = make_uint2(bf2(v.x, v.y), bf2(v.z, v.w));
            *(uint2*)(Al + r * KS1 + k4 * 4) =
                make_uint2(bf2(v.x - bf_round(v.x), v.y - bf_round(v.y)),
                           bf2(v.z - bf_round(v.z), v.w - bf_round(v.w)));
            *(uint2*)(Bh + r * KS1 + k4 * 4) = *(const uint2*)(g_WT2hi + r * 512 + col);
            *(uint2*)(Bl + r * KS1 + k4 * 4) = *(const uint2*)(g_WT2lo + r * 512 + col);
        }
        __syncthreads();
#pragma unroll
        for (int ks = 0; ks < 8; ks++) {
            int kb = ks * 8;
            uint32_t ah[4][4], al[4][4], bh[4][2], bl[4][2];
#pragma unroll
            for (int rb = 0; rb < 4; rb++) {
                int base = (wm * 64 + rb * 16 + g) * KS1_32 + kb + t;
                ah[rb][0] = Ah32[base];             ah[rb][1] = Ah32[base + 8 * KS1_32];
                ah[rb][2] = Ah32[base + 4];         ah[rb][3] = Ah32[base + 8 * KS1_32 + 4];
                al[rb][0] = Al32[base];             al[rb][1] = Al32[base + 8 * KS1_32];
                al[rb][2] = Al32[base + 4];         al[rb][3] = Al32[base + 8 * KS1_32 + 4];
            }
#pragma unroll
            for (int nb = 0; nb < 4; nb++) {
                int base = (wn * 32 + nb * 8 + g) * KS1_32 + kb + t;
                bh[nb][0] = Bh32[base];  bh[nb][1] = Bh32[base + 4];
                bl[nb][0] = Bl32[base];  bl[nb][1] = Bl32[base + 4];
            }
#pragma unroll
            for (int rb = 0; rb < 4; rb++)
#pragma unroll
                for (int nb = 0; nb < 4; nb++) {
                    mma_bf16(c[rb][nb], ah[rb][0], ah[rb][1], ah[rb][2], ah[rb][3],
                             bh[nb][0], bh[nb][1]);
                    mma_bf16(c[rb][nb], al[rb][0], al[rb][1], al[rb][2], al[rb][3],
                             bh[nb][0], bh[nb][1]);
                    mma_bf16(c[rb][nb], ah[rb][0], ah[rb][1], ah[rb][2], ah[rb][3],
                             bl[nb][0], bl[nb][1]);
                }
        }
        __syncthreads();
    }
#pragma unroll
    for (int rb = 0; rb < 4; rb++) {
        int gr0 = row0 + wm * 64 + rb * 16 + g;
#pragma unroll
        for (int nb = 0; nb < 4; nb++) {
            int col = wn * 32 + nb * 8 + 2 * t;
            float* cc = c[rb][nb];
            float2 bv = *(const float2*)(bout + col);
            if (gr0 < N_NODES)
                *(float2*)(out + gr0 * OUTF + col) =
                    make_float2(cc[0] + bv.x, cc[1] + bv.y);
            if (gr0 + 8 < N_NODES)
                *(float2*)(out + (gr0 + 8) * OUTF + col) =
                    make_float2(cc[2] + bv.x, cc[3] + bv.y);
        }
    }
}

// ---------------- launch (fork/join overlap) ----------------
extern "C" void kernel_launch(void* const* d_in, const int* in_sizes, int n_in,
                              void* d_out, int out_size) {
    const float* feat    = (const float*)d_in[0];
    const int*   src     = (const int*)d_in[1];
    const int*   dst     = (const int*)d_in[2];
    const float* Wfc     = (const float*)d_in[3];
    const float* attn_l  = (const float*)d_in[4];
    const float* attn_r  = (const float*)d_in[5];
    const float* Wres    = (const float*)d_in[6];
    const float* biasg   = (const float*)d_in[7];
    const float* gamma   = (const float*)d_in[8];
    const float* beta    = (const float*)d_in[9];
    const float* Wout    = (const float*)d_in[10];
    const float* bout    = (const float*)d_in[11];
    float* out = (float*)d_out;

    static cudaStream_t sB = nullptr;
    static cudaEvent_t evRoot = nullptr, evCsr = nullptr;
    if (sB == nullptr) {
        cudaStreamCreateWithFlags(&sB, cudaStreamNonBlocking);
        cudaEventCreateWithFlags(&evRoot, cudaEventDisableTiming);
        cudaEventCreateWithFlags(&evCsr, cudaEventDisableTiming);
        cudaFuncSetAttribute(gemm1_mma, cudaFuncAttributeMaxDynamicSharedMemorySize, SMEM_G);
        cudaFuncSetAttribute(gemm2_mma, cudaFuncAttributeMaxDynamicSharedMemorySize, SMEM_G);
    }

    // main stream: weights prep (also zeroes g_deg)
    prep_kernel<<<SCAN_NB + 128 + 64 + 8, 256>>>(Wfc, Wres, Wout, attn_l, attn_r);
    cudaEventRecord(evRoot, 0);

    // fork: elr + CSR build on side stream (independent of gemm1)
    cudaStreamWaitEvent(sB, evRoot, 0);
    elr_kernel<<<(N_NODES + 7) / 8, 256, 0, sB>>>(feat);
    hist_kernel<<<(N_EDGES + 255) / 256, 256, 0, sB>>>(dst);
    scan1_kernel<<<SCAN_NB, 256, 0, sB>>>();
    scan2_kernel<<<1, 128, 0, sB>>>();
    scan3_kernel<<<SCAN_NB, 256, 0, sB>>>();
    scatter_kernel<<<(N_EDGES + 255) / 256, 256, 0, sB>>>(src, dst);
    cudaEventRecord(evCsr, sB);

    // main stream: projection GEMM (overlaps elr + CSR chain)
    gemm1_mma<<<dim3(2, NROWB), 256, SMEM_G>>>(feat, biasg);

    // join: aggregation needs both paths
    cudaStreamWaitEvent(0, evCsr, 0);
    agg_kernel<<<(N_NODES + 31) / 32, 256>>>();
    bn_part_kernel<<<BN_BLOCKS, HD>>>();
    bn_final_kernel<<<1, HD>>>(gamma, beta);
    gemm2_mma<<<NROWB, 256, SMEM_G>>>(bout, out);
}

// round 9
// speedup vs baseline: 2.0377x; 1.1899x over previous
#include <cuda_runtime.h>
#include <cuda_bf16.h>
#include <cuda_fp16.h>
#include <math.h>
#include <stdint.h>

#define N_NODES 30000
#define N_EDGES 480000
#define NHEAD   4
#define HD      512
#define OUTF    128
#define NEG_SLOPE 0.2f
#define BN_EPS  1e-5f
#define BN_BLOCKS 256
#define SCAN_NB 118
#define NROWB   235          // ceil(30000/128)

// ---------------- scratch ----------------
__device__ unsigned short g_h16[N_NODES * HD];   // fp16 projected feats (agg only)
__device__ float g_rst[N_NODES * HD];
__device__ float g_el[N_NODES * NHEAD];
__device__ float g_er[N_NODES * NHEAD];
__device__ float g_P[8 * 128];
__device__ int   g_deg[N_NODES];
__device__ int   g_cursor[N_NODES];
__device__ int   g_ptr[N_NODES + 1];
__device__ int   g_srcs[N_EDGES];
__device__ int   g_blocksum[SCAN_NB];
__device__ int   g_blockoff[SCAN_NB];
__device__ float g_psum[BN_BLOCKS * HD];
__device__ float g_psq[BN_BLOCKS * HD];
__device__ float g_scale[HD];
__device__ float g_shift[HD];
__device__ unsigned short g_WT1h[1024 * 128];     // fp16 [n][k] for [Wfc|Wres]
__device__ unsigned short g_WT2h[128 * 512];      // fp16 [n][k] for Wout

// ---------------- helpers ----------------
__device__ __forceinline__ uint32_t f2h2(float lo, float hi) {
    __half2 h = __floats2half2_rn(lo, hi);
    return *(uint32_t*)&h;
}
__device__ __forceinline__ float2 h2f(uint32_t u) {
    return __half22float2(*(__half2*)&u);
}
__device__ __forceinline__ unsigned short f2h_us(float x) {
    __half h = __float2half_rn(x);
    return *(unsigned short*)&h;
}
__device__ __forceinline__ void mma_f16(float* c, uint32_t a0, uint32_t a1,
                                        uint32_t a2, uint32_t a3,
                                        uint32_t b0, uint32_t b1) {
    asm volatile(
        "mma.sync.aligned.m16n8k16.row.col.f32.f16.f16.f32 "
        "{%0,%1,%2,%3}, {%4,%5,%6,%7}, {%8,%9}, {%0,%1,%2,%3};"
        : "+f"(c[0]), "+f"(c[1]), "+f"(c[2]), "+f"(c[3])
        : "r"(a0), "r"(a1), "r"(a2), "r"(a3), "r"(b0), "r"(b1));
}

// ---------------- fused prep: zero_deg | transpose1 | transpose2 | pvec ------
__global__ __launch_bounds__(256) void prep_kernel(
    const float* __restrict__ Wfc, const float* __restrict__ Wres,
    const float* __restrict__ Wout, const float* __restrict__ attn_l,
    const float* __restrict__ attn_r) {
    int b = blockIdx.x;
    int tid = threadIdx.x;
    if (b < SCAN_NB) {
        int i = b * 256 + tid;
        if (i < N_NODES) g_deg[i] = 0;
        return;
    }
    b -= SCAN_NB;
    if (b < 128) {
        __shared__ float t[32][33];
        int k0 = (b & 3) * 32;
        int n0 = (b >> 2) * 32;
        int tx = tid & 31, ty = tid >> 5;
        const float* W = (n0 < 512) ? Wfc : Wres;
        int nn0 = (n0 < 512) ? n0 : n0 - 512;
#pragma unroll
        for (int i = 0; i < 32; i += 8)
            t[ty + i][tx] = W[(k0 + ty + i) * 512 + nn0 + tx];
        __syncthreads();
#pragma unroll
        for (int i = 0; i < 32; i += 8) {
            float v = t[tx][ty + i];
            int n = n0 + ty + i, k = k0 + tx;
            g_WT1h[n * 128 + k] = f2h_us(v);
        }
        return;
    }
    b -= 128;
    if (b < 64) {
        __shared__ float t2[32][33];
        int k0 = (b & 15) * 32;
        int n0 = (b >> 4) * 32;
        int tx = tid & 31, ty = tid >> 5;
#pragma unroll
        for (int i = 0; i < 32; i += 8)
            t2[ty + i][tx] = Wout[(k0 + ty + i) * 128 + n0 + tx];
        __syncthreads();
#pragma unroll
        for (int i = 0; i < 32; i += 8) {
            float v = t2[tx][ty + i];
            int n = n0 + ty + i, k = k0 + tx;
            g_WT2h[n * 512 + k] = f2h_us(v);
        }
        return;
    }
    b -= 64;
    if (tid >= 128) return;
    int h = b & 3;
    const float* av = ((b < 4) ? attn_l : attn_r) + h * 128;
    const float* wr = Wfc + tid * HD + h * 128;
    float s = 0.f;
#pragma unroll
    for (int d4 = 0; d4 < 32; d4++) {
        float4 w = *(const float4*)(wr + d4 * 4);
        float4 a = *(const float4*)(av + d4 * 4);
        s += w.x * a.x + w.y * a.y + w.z * a.z + w.w * a.w;
    }
    g_P[b * 128 + tid] = s;
}

__global__ __launch_bounds__(256) void elr_kernel(const float* __restrict__ feat) {
    __shared__ float Ps[8][128];
    int t = threadIdx.x;
    for (int i = t; i < 1024; i += 256) Ps[i >> 7][i & 127] = g_P[i];
    __syncthreads();
    int n = blockIdx.x * 8 + (t >> 5);
    int lane = t & 31;
    if (n >= N_NODES) return;
    float4 f = *(const float4*)(feat + n * 128 + lane * 4);
    float s[8];
#pragma unroll
    for (int j = 0; j < 8; j++) {
        const float* p = &Ps[j][lane * 4];
        s[j] = f.x * p[0] + f.y * p[1] + f.z * p[2] + f.w * p[3];
    }
#pragma unroll
    for (int o = 16; o; o >>= 1)
#pragma unroll
        for (int j = 0; j < 8; j++) s[j] += __shfl_xor_sync(0xffffffffu, s[j], o);
    if (lane < 4) {
        g_el[n * 4 + lane] = s[lane];
        g_er[n * 4 + lane] = s[lane + 4];
    }
}

// ---------------- CSR build ----------------
__global__ void hist_kernel(const int* __restrict__ dst) {
    int e = blockIdx.x * blockDim.x + threadIdx.x;
    if (e < N_EDGES) atomicAdd(&g_deg[dst[e]], 1);
}

__global__ void scan1_kernel() {
    __shared__ int wsum[8];
    int t = threadIdx.x, b = blockIdx.x;
    int idx = b * 256 + t;
    int lane = t & 31, wid = t >> 5;
    int v = (idx < N_NODES) ? g_deg[idx] : 0;
    int x = v;
#pragma unroll
    for (int o = 1; o < 32; o <<= 1) {
        int y = __shfl_up_sync(0xffffffffu, x, o);
        if (lane >= o) x += y;
    }
    if (lane == 31) wsum[wid] = x;
    __syncthreads();
    if (t == 0) {
        int run = 0;
#pragma unroll
        for (int i = 0; i < 8; i++) { int tmp = wsum[i]; wsum[i] = run; run += tmp; }
        g_blocksum[b] = run;
    }
    __syncthreads();
    int incl = x + wsum[wid];
    if (idx < N_NODES) g_ptr[idx + 1] = incl;
}

__global__ void scan2_kernel() {
    __shared__ int ws[4];
    int t = threadIdx.x;
    int lane = t & 31, w = t >> 5;
    int v = (t < SCAN_NB) ? g_blocksum[t] : 0;
    int x = v;
#pragma unroll
    for (int o = 1; o < 32; o <<= 1) {
        int y = __shfl_up_sync(0xffffffffu, x, o);
        if (lane >= o) x += y;
    }
    if (lane == 31) ws[w] = x;
    __syncthreads();
    if (t == 0) {
        int run = 0;
#pragma unroll
        for (int i = 0; i < 4; i++) { int tmp = ws[i]; ws[i] = run; run += tmp; }
    }
    __syncthreads();
    if (t < SCAN_NB) g_blockoff[t] = x + ws[w] - v;   // exclusive
}

__global__ void scan3_kernel() {
    int t = threadIdx.x, b = blockIdx.x;
    int idx = b * 256 + t;
    if (idx >= N_NODES) return;
    int off = g_blockoff[b];
    int incl = g_ptr[idx + 1] + off;
    g_ptr[idx + 1] = incl;
    g_cursor[idx] = incl - g_deg[idx];
    if (idx == 0) g_ptr[0] = 0;
}

__global__ void scatter_kernel(const int* __restrict__ src,
                               const int* __restrict__ dst) {
    int e = blockIdx.x * blockDim.x + threadIdx.x;
    if (e < N_EDGES) {
        int p = atomicAdd(&g_cursor[dst[e]], 1);
        g_srcs[p] = src[e];
    }
}

// ---------------- GEMM1 (fp16 2-term mma.sync, full-K smem) ----------------
#define KS1 136
#define KS1_32 68
#define SMEM_G (3 * 128 * KS1 * 2)   // 104448 bytes: Ah, Al, Bh

__global__ __launch_bounds__(256) void gemm1_mma(const float* __restrict__ feat,
                                                 const float* __restrict__ biasg) {
    extern __shared__ unsigned short sm[];
    unsigned short* Ah = sm;
    unsigned short* Al = Ah + 128 * KS1;
    unsigned short* Bh = Al + 128 * KS1;
    const int tid = threadIdx.x;
    const int warp = tid >> 5, lane = tid & 31;
    const int wm = warp >> 2, wn = warp & 3;
    const int g = lane >> 2, t = lane & 3;
    const int row0 = blockIdx.y * 128;
    const int half = blockIdx.x;

    // fill A once: feat fp32 -> fp16 hi + lo
    for (int idx = tid; idx < 4096; idx += 256) {
        int r = idx >> 5, k4 = idx & 31;
        int gr = row0 + r;
        float4 f = make_float4(0.f, 0.f, 0.f, 0.f);
        if (gr < N_NODES) f = *(const float4*)(feat + gr * 128 + k4 * 4);
        uint32_t h0 = f2h2(f.x, f.y), h1 = f2h2(f.z, f.w);
        float2 r0 = h2f(h0), r1 = h2f(h1);
        uint32_t l0 = f2h2(f.x - r0.x, f.y - r0.y);
        uint32_t l1 = f2h2(f.z - r1.x, f.w - r1.y);
        *(uint2*)(Ah + r * KS1 + k4 * 4) = make_uint2(h0, h1);
        *(uint2*)(Al + r * KS1 + k4 * 4) = make_uint2(l0, l1);
    }

    const uint32_t* Ah32 = (const uint32_t*)Ah;
    const uint32_t* Al32 = (const uint32_t*)Al;
    const uint32_t* Bh32 = (const uint32_t*)Bh;

    for (int i = 0; i < 4; i++) {
        int bx = half * 4 + i;
        for (int idx = tid; idx < 4096; idx += 256) {
            int r = idx >> 5, k4 = idx & 31;
            int n = bx * 128 + r;
            *(uint2*)(Bh + r * KS1 + k4 * 4) = *(const uint2*)(g_WT1h + n * 128 + k4 * 4);
        }
        __syncthreads();

        float c[4][4][4];
#pragma unroll
        for (int a = 0; a < 4; a++)
#pragma unroll
            for (int bq = 0; bq < 4; bq++)
#pragma unroll
                for (int q = 0; q < 4; q++) c[a][bq][q] = 0.f;

#pragma unroll
        for (int ks = 0; ks < 8; ks++) {
            int kb = ks * 8;
            uint32_t ah[4][4], al[4][4], bh[4][2];
#pragma unroll
            for (int rb = 0; rb < 4; rb++) {
                int base = (wm * 64 + rb * 16 + g) * KS1_32 + kb + t;
                ah[rb][0] = Ah32[base];             ah[rb][1] = Ah32[base + 8 * KS1_32];
                ah[rb][2] = Ah32[base + 4];         ah[rb][3] = Ah32[base + 8 * KS1_32 + 4];
                al[rb][0] = Al32[base];             al[rb][1] = Al32[base + 8 * KS1_32];
                al[rb][2] = Al32[base + 4];         al[rb][3] = Al32[base + 8 * KS1_32 + 4];
            }
#pragma unroll
            for (int nb = 0; nb < 4; nb++) {
                int base = (wn * 32 + nb * 8 + g) * KS1_32 + kb + t;
                bh[nb][0] = Bh32[base];  bh[nb][1] = Bh32[base + 4];
            }
#pragma unroll
            for (int rb = 0; rb < 4; rb++)
#pragma unroll
                for (int nb = 0; nb < 4; nb++) {
                    mma_f16(c[rb][nb], ah[rb][0], ah[rb][1], ah[rb][2], ah[rb][3],
                            bh[nb][0], bh[nb][1]);
                    mma_f16(c[rb][nb], al[rb][0], al[rb][1], al[rb][2], al[rb][3],
                            bh[nb][0], bh[nb][1]);
                }
        }
#pragma unroll
        for (int rb = 0; rb < 4; rb++) {
            int gr0 = row0 + wm * 64 + rb * 16 + g;
#pragma unroll
            for (int nb = 0; nb < 4; nb++) {
                int col = bx * 128 + wn * 32 + nb * 8 + 2 * t;
                float* cc = c[rb][nb];
                if (col < 512) {
                    if (gr0 < N_NODES)
                        *(uint32_t*)(g_h16 + gr0 * HD + col) = f2h2(cc[0], cc[1]);
                    if (gr0 + 8 < N_NODES)
                        *(uint32_t*)(g_h16 + (gr0 + 8) * HD + col) = f2h2(cc[2], cc[3]);
                } else {
                    int cb = col - 512;
                    float2 bv = *(const float2*)(biasg + cb);
                    if (gr0 < N_NODES)
                        *(float2*)(g_rst + gr0 * HD + cb) =
                            make_float2(cc[0] + bv.x, cc[1] + bv.y);
                    if (gr0 + 8 < N_NODES)
                        *(float2*)(g_rst + (gr0 + 8) * HD + cb) =
                            make_float2(cc[2] + bv.x, cc[3] + bv.y);
                }
            }
        }
        __syncthreads();
    }
}

// ---------------- aggregation: 4 nodes per warp, fp16 gather, prefetch ------
__global__ __launch_bounds__(256) void agg_kernel() {
    int wg = blockIdx.x * 8 + (threadIdx.x >> 5);
    int lane = threadIdx.x & 31;
#pragma unroll 1
    for (int q = 0; q < 4; q++) {
        int v = wg * 4 + q;
        if (v >= N_NODES) return;
        int start = g_ptr[v], end = g_ptr[v + 1];
        if (start == end) continue;
        float4 er = *(const float4*)(g_er + v * 4);

        float4 a0 = make_float4(0.f, 0.f, 0.f, 0.f);
        float4 a1 = a0, a2 = a0, a3 = a0;
        float d0 = 0.f, d1 = 0.f, d2 = 0.f, d3 = 0.f;

        int s = g_srcs[start];
        float4 el = *(const float4*)(g_el + s * 4);
        for (int j = start; j < end; j++) {
            int jn = (j + 1 < end) ? j + 1 : j;
            int s2 = g_srcs[jn];
            float4 el2 = *(const float4*)(g_el + s2 * 4);

            const unsigned short* hp = g_h16 + s * HD + lane * 4;
            uint2 q0 = *(const uint2*)(hp);
            uint2 q1 = *(const uint2*)(hp + 128);
            uint2 q2 = *(const uint2*)(hp + 256);
            uint2 q3 = *(const uint2*)(hp + 384);

            float e0 = el.x + er.x; e0 = (e0 > 0.f) ? e0 : NEG_SLOPE * e0;
            float e1 = el.y + er.y; e1 = (e1 > 0.f) ? e1 : NEG_SLOPE * e1;
            float e2 = el.z + er.z; e2 = (e2 > 0.f) ? e2 : NEG_SLOPE * e2;
            float e3 = el.w + er.w; e3 = (e3 > 0.f) ? e3 : NEG_SLOPE * e3;
            float w0 = __expf(e0), w1 = __expf(e1), w2 = __expf(e2), w3 = __expf(e3);
            d0 += w0; d1 += w1; d2 += w2; d3 += w3;

            float2 p;
            p = h2f(q0.x); a0.x += w0 * p.x; a0.y += w0 * p.y;
            p = h2f(q0.y); a0.z += w0 * p.x; a0.w += w0 * p.y;
            p = h2f(q1.x); a1.x += w1 * p.x; a1.y += w1 * p.y;
            p = h2f(q1.y); a1.z += w1 * p.x; a1.w += w1 * p.y;
            p = h2f(q2.x); a2.x += w2 * p.x; a2.y += w2 * p.y;
            p = h2f(q2.y); a2.z += w2 * p.x; a2.w += w2 * p.y;
            p = h2f(q3.x); a3.x += w3 * p.x; a3.y += w3 * p.y;
            p = h2f(q3.y); a3.z += w3 * p.x; a3.w += w3 * p.y;

            s = s2; el = el2;
        }
        float i0 = 1.f / d0, i1 = 1.f / d1, i2 = 1.f / d2, i3 = 1.f / d3;
        float* o = g_rst + v * HD + lane * 4;
        float4 c0 = *(float4*)(o);
        float4 c1 = *(float4*)(o + 128);
        float4 c2 = *(float4*)(o + 256);
        float4 c3 = *(float4*)(o + 384);
        c0.x += a0.x * i0; c0.y += a0.y * i0; c0.z += a0.z * i0; c0.w += a0.w * i0;
        c1.x += a1.x * i1; c1.y += a1.y * i1; c1.z += a1.z * i1; c1.w += a1.w * i1;
        c2.x += a2.x * i2; c2.y += a2.y * i2; c2.z += a2.z * i2; c2.w += a2.w * i2;
        c3.x += a3.x * i3; c3.y += a3.y * i3; c3.z += a3.z * i3; c3.w += a3.w * i3;
        *(float4*)(o)       = c0;
        *(float4*)(o + 128) = c1;
        *(float4*)(o + 256) = c2;
        *(float4*)(o + 384) = c3;
    }
}

// ---------------- BatchNorm stats ----------------
__global__ void bn_part_kernel() {
    int c = threadIdx.x;
    float s = 0.f, q = 0.f;
    for (int r = blockIdx.x; r < N_NODES; r += gridDim.x) {
        float x = g_rst[r * HD + c];
        s += x;
        q += x * x;
    }
    g_psum[blockIdx.x * HD + c] = s;
    g_psq[blockIdx.x * HD + c] = q;
}

__global__ void bn_final_kernel(const float* __restrict__ gamma,
                                const float* __restrict__ beta) {
    int c = threadIdx.x;
    float s = 0.f, q = 0.f;
    for (int b = 0; b < BN_BLOCKS; b++) {
        s += g_psum[b * HD + c];
        q += g_psq[b * HD + c];
    }
    float mu = s / (float)N_NODES;
    float var = q / (float)N_NODES - mu * mu;
    float rstd = rsqrtf(var + BN_EPS);
    float sc = gamma[c] * rstd;
    g_scale[c] = sc;
    g_shift[c] = beta[c] - mu * sc;
}

// ---------------- GEMM2 (fp16 2-term mma.sync, BK=128, 4 kc chunks) ---------
__global__ __launch_bounds__(256) void gemm2_mma(const float* __restrict__ bout,
                                                 float* __restrict__ out) {
    extern __shared__ unsigned short sm[];
    unsigned short* Ah = sm;
    unsigned short* Al = Ah + 128 * KS1;
    unsigned short* Bh = Al + 128 * KS1;
    const int tid = threadIdx.x;
    const int warp = tid >> 5, lane = tid & 31;
    const int wm = warp >> 2, wn = warp & 3;
    const int g = lane >> 2, t = lane & 3;
    const int row0 = blockIdx.x * 128;

    const uint32_t* Ah32 = (const uint32_t*)Ah;
    const uint32_t* Al32 = (const uint32_t*)Al;
    const uint32_t* Bh32 = (const uint32_t*)Bh;

    float c[4][4][4];
#pragma unroll
    for (int a = 0; a < 4; a++)
#pragma unroll
        for (int bq = 0; bq < 4; bq++)
#pragma unroll
            for (int q = 0; q < 4; q++) c[a][bq][q] = 0.f;

    for (int kc = 0; kc < 4; kc++) {
        int k0 = kc * 128;
        for (int idx = tid; idx < 4096; idx += 256) {
            int r = idx >> 5, k4 = idx & 31;
            int gr = row0 + r;
            int col = k0 + k4 * 4;
            float4 v = make_float4(0.f, 0.f, 0.f, 0.f);
            if (gr < N_NODES) {
                float4 x = *(const float4*)(g_rst + gr * HD + col);
                float4 sc = *(const float4*)(g_scale + col);
                float4 sh = *(const float4*)(g_shift + col);
                v.x = fmaxf(sc.x * x.x + sh.x, 0.f);
                v.y = fmaxf(sc.y * x.y + sh.y, 0.f);
                v.z = fmaxf(sc.z * x.z + sh.z, 0.f);
                v.w = fmaxf(sc.w * x.w + sh.w, 0.f);
            }
            uint32_t h0 = f2h2(v.x, v.y), h1 = f2h2(v.z, v.w);
            float2 r0 = h2f(h0), r1 = h2f(h1);
            uint32_t l0 = f2h2(v.x - r0.x, v.y - r0.y);
            uint32_t l1 = f2h2(v.z - r1.x, v.w - r1.y);
            *(uint2*)(Ah + r * KS1 + k4 * 4) = make_uint2(h0, h1);
            *(uint2*)(Al + r * KS1 + k4 * 4) = make_uint2(l0, l1);
            *(uint2*)(Bh + r * KS1 + k4 * 4) = *(const uint2*)(g_WT2h + r * 512 + col);
        }
        __syncthreads();
#pragma unroll
        for (int ks = 0; ks < 8; ks++) {
            int kb = ks * 8;
            uint32_t ah[4][4], al[4][4], bh[4][2];
#pragma unroll
            for (int rb = 0; rb < 4; rb++) {
                int base = (wm * 64 + rb * 16 + g) * KS1_32 + kb + t;
                ah[rb][0] = Ah32[base];             ah[rb][1] = Ah32[base + 8 * KS1_32];
                ah[rb][2] = Ah32[base + 4];         ah[rb][3] = Ah32[base + 8 * KS1_32 + 4];
                al[rb][0] = Al32[base];             al[rb][1] = Al32[base + 8 * KS1_32];
                al[rb][2] = Al32[base + 4];         al[rb][3] = Al32[base + 8 * KS1_32 + 4];
            }
#pragma unroll
            for (int nb = 0; nb < 4; nb++) {
                int base = (wn * 32 + nb * 8 + g) * KS1_32 + kb + t;
                bh[nb][0] = Bh32[base];  bh[nb][1] = Bh32[base + 4];
            }
#pragma unroll
            for (int rb = 0; rb < 4; rb++)
#pragma unroll
                for (int nb = 0; nb < 4; nb++) {
                    mma_f16(c[rb][nb], ah[rb][0], ah[rb][1], ah[rb][2], ah[rb][3],
                            bh[nb][0], bh[nb][1]);
                    mma_f16(c[rb][nb], al[rb][0], al[rb][1], al[rb][2], al[rb][3],
                            bh[nb][0], bh[nb][1]);
                }
        }
        __syncthreads();
    }
#pragma unroll
    for (int rb = 0; rb < 4; rb++) {
        int gr0 = row0 + wm * 64 + rb * 16 + g;
#pragma unroll
        for (int nb = 0; nb < 4; nb++) {
            int col = wn * 32 + nb * 8 + 2 * t;
            float* cc = c[rb][nb];
            float2 bv = *(const float2*)(bout + col);
            if (gr0 < N_NODES)
                *(float2*)(out + gr0 * OUTF + col) =
                    make_float2(cc[0] + bv.x, cc[1] + bv.y);
            if (gr0 + 8 < N_NODES)
                *(float2*)(out + (gr0 + 8) * OUTF + col) =
                    make_float2(cc[2] + bv.x, cc[3] + bv.y);
        }
    }
}

// ---------------- launch (fork/join overlap) ----------------
extern "C" void kernel_launch(void* const* d_in, const int* in_sizes, int n_in,
                              void* d_out, int out_size) {
    const float* feat    = (const float*)d_in[0];
    const int*   src     = (const int*)d_in[1];
    const int*   dst     = (const int*)d_in[2];
    const float* Wfc     = (const float*)d_in[3];
    const float* attn_l  = (const float*)d_in[4];
    const float* attn_r  = (const float*)d_in[5];
    const float* Wres    = (const float*)d_in[6];
    const float* biasg   = (const float*)d_in[7];
    const float* gamma   = (const float*)d_in[8];
    const float* beta    = (const float*)d_in[9];
    const float* Wout    = (const float*)d_in[10];
    const float* bout    = (const float*)d_in[11];
    float* out = (float*)d_out;

    static cudaStream_t sB = nullptr;
    static cudaEvent_t evRoot = nullptr, evCsr = nullptr;
    if (sB == nullptr) {
        cudaStreamCreateWithFlags(&sB, cudaStreamNonBlocking);
        cudaEventCreateWithFlags(&evRoot, cudaEventDisableTiming);
        cudaEventCreateWithFlags(&evCsr, cudaEventDisableTiming);
        cudaFuncSetAttribute(gemm1_mma, cudaFuncAttributeMaxDynamicSharedMemorySize, SMEM_G);
        cudaFuncSetAttribute(gemm2_mma, cudaFuncAttributeMaxDynamicSharedMemorySize, SMEM_G);
    }

    // main stream: weights prep (also zeroes g_deg)
    prep_kernel<<<SCAN_NB + 128 + 64 + 8, 256>>>(Wfc, Wres, Wout, attn_l, attn_r);
    cudaEventRecord(evRoot, 0);

    // fork: elr + CSR build on side stream (independent of gemm1)
    cudaStreamWaitEvent(sB, evRoot, 0);
    elr_kernel<<<(N_NODES + 7) / 8, 256, 0, sB>>>(feat);
    hist_kernel<<<(N_EDGES + 255) / 256, 256, 0, sB>>>(dst);
    scan1_kernel<<<SCAN_NB, 256, 0, sB>>>();
    scan2_kernel<<<1, 128, 0, sB>>>();
    scan3_kernel<<<SCAN_NB, 256, 0, sB>>>();
    scatter_kernel<<<(N_EDGES + 255) / 256, 256, 0, sB>>>(src, dst);
    cudaEventRecord(evCsr, sB);

    // main stream: projection GEMM (overlaps elr + CSR chain)
    gemm1_mma<<<dim3(2, NROWB), 256, SMEM_G>>>(feat, biasg);

    // join: aggregation needs both paths
    cudaStreamWaitEvent(0, evCsr, 0);
    agg_kernel<<<(N_NODES + 31) / 32, 256>>>();
    bn_part_kernel<<<BN_BLOCKS, HD>>>();
    bn_final_kernel<<<1, HD>>>(gamma, beta);
    gemm2_mma<<<NROWB, 256, SMEM_G>>>(bout, out);
}

// round 10
// speedup vs baseline: 2.2197x; 1.0893x over previous
#include <cuda_runtime.h>
#include <cuda_bf16.h>
#include <cuda_fp16.h>
#include <math.h>
#include <stdint.h>

#define N_NODES 30000
#define N_EDGES 480000
#define NHEAD   4
#define HD      512
#define OUTF    128
#define NEG_SLOPE 0.2f
#define BN_EPS  1e-5f
#define BN_BLOCKS 256
#define SCAN_NB 118
#define NROWB   235          // ceil(30000/128)

// ---------------- scratch ----------------
__device__ unsigned short g_h16[N_NODES * HD];   // fp16 projected feats (agg only)
__device__ float g_rst[N_NODES * HD];
__device__ float g_el[N_NODES * NHEAD];
__device__ float g_er[N_NODES * NHEAD];
__device__ float g_P[8 * 128];
__device__ int   g_deg[N_NODES];
__device__ int   g_cursor[N_NODES];
__device__ int   g_ptr[N_NODES + 1];
__device__ int   g_srcs[N_EDGES];
__device__ int   g_blocksum[SCAN_NB];
__device__ int   g_blockoff[SCAN_NB];
__device__ float g_psum[BN_BLOCKS * HD];
__device__ float g_psq[BN_BLOCKS * HD];
__device__ float g_scale[HD];
__device__ float g_shift[HD];
__device__ unsigned short g_WT1h[1024 * 128];     // fp16 [n][k] for [Wfc|Wres]
__device__ unsigned short g_WT2h[128 * 512];      // fp16 [n][k] for Wout

// ---------------- helpers ----------------
__device__ __forceinline__ uint32_t f2h2(float lo, float hi) {
    __half2 h = __floats2half2_rn(lo, hi);
    return *(uint32_t*)&h;
}
__device__ __forceinline__ float2 h2f(uint32_t u) {
    return __half22float2(*(__half2*)&u);
}
__device__ __forceinline__ unsigned short f2h_us(float x) {
    __half h = __float2half_rn(x);
    return *(unsigned short*)&h;
}
__device__ __forceinline__ void mma_f16(float* c, uint32_t a0, uint32_t a1,
                                        uint32_t a2, uint32_t a3,
                                        uint32_t b0, uint32_t b1) {
    asm volatile(
        "mma.sync.aligned.m16n8k16.row.col.f32.f16.f16.f32 "
        "{%0,%1,%2,%3}, {%4,%5,%6,%7}, {%8,%9}, {%0,%1,%2,%3};"
        : "+f"(c[0]), "+f"(c[1]), "+f"(c[2]), "+f"(c[3])
        : "r"(a0), "r"(a1), "r"(a2), "r"(a3), "r"(b0), "r"(b1));
}

// ---------------- fused prep: zero_deg | transpose1 | transpose2 | pvec ------
__global__ __launch_bounds__(256) void prep_kernel(
    const float* __restrict__ Wfc, const float* __restrict__ Wres,
    const float* __restrict__ Wout, const float* __restrict__ attn_l,
    const float* __restrict__ attn_r) {
    int b = blockIdx.x;
    int tid = threadIdx.x;
    if (b < SCAN_NB) {
        int i = b * 256 + tid;
        if (i < N_NODES) g_deg[i] = 0;
        return;
    }
    b -= SCAN_NB;
    if (b < 128) {
        __shared__ float t[32][33];
        int k0 = (b & 3) * 32;
        int n0 = (b >> 2) * 32;
        int tx = tid & 31, ty = tid >> 5;
        const float* W = (n0 < 512) ? Wfc : Wres;
        int nn0 = (n0 < 512) ? n0 : n0 - 512;
#pragma unroll
        for (int i = 0; i < 32; i += 8)
            t[ty + i][tx] = W[(k0 + ty + i) * 512 + nn0 + tx];
        __syncthreads();
#pragma unroll
        for (int i = 0; i < 32; i += 8) {
            float v = t[tx][ty + i];
            int n = n0 + ty + i, k = k0 + tx;
            g_WT1h[n * 128 + k] = f2h_us(v);
        }
        return;
    }
    b -= 128;
    if (b < 64) {
        __shared__ float t2[32][33];
        int k0 = (b & 15) * 32;
        int n0 = (b >> 4) * 32;
        int tx = tid & 31, ty = tid >> 5;
#pragma unroll
        for (int i = 0; i < 32; i += 8)
            t2[ty + i][tx] = Wout[(k0 + ty + i) * 128 + n0 + tx];
        __syncthreads();
#pragma unroll
        for (int i = 0; i < 32; i += 8) {
            float v = t2[tx][ty + i];
            int n = n0 + ty + i, k = k0 + tx;
            g_WT2h[n * 512 + k] = f2h_us(v);
        }
        return;
    }
    b -= 64;
    if (tid >= 128) return;
    int h = b & 3;
    const float* av = ((b < 4) ? attn_l : attn_r) + h * 128;
    const float* wr = Wfc + tid * HD + h * 128;
    float s = 0.f;
#pragma unroll
    for (int d4 = 0; d4 < 32; d4++) {
        float4 w = *(const float4*)(wr + d4 * 4);
        float4 a = *(const float4*)(av + d4 * 4);
        s += w.x * a.x + w.y * a.y + w.z * a.z + w.w * a.w;
    }
    g_P[b * 128 + tid] = s;
}

__global__ __launch_bounds__(256) void elr_kernel(const float* __restrict__ feat) {
    __shared__ float Ps[8][128];
    int t = threadIdx.x;
    for (int i = t; i < 1024; i += 256) Ps[i >> 7][i & 127] = g_P[i];
    __syncthreads();
    int n = blockIdx.x * 8 + (t >> 5);
    int lane = t & 31;
    if (n >= N_NODES) return;
    float4 f = *(const float4*)(feat + n * 128 + lane * 4);
    float s[8];
#pragma unroll
    for (int j = 0; j < 8; j++) {
        const float* p = &Ps[j][lane * 4];
        s[j] = f.x * p[0] + f.y * p[1] + f.z * p[2] + f.w * p[3];
    }
#pragma unroll
    for (int o = 16; o; o >>= 1)
#pragma unroll
        for (int j = 0; j < 8; j++) s[j] += __shfl_xor_sync(0xffffffffu, s[j], o);
    if (lane < 4) {
        g_el[n * 4 + lane] = s[lane];
        g_er[n * 4 + lane] = s[lane + 4];
    }
}

// ---------------- CSR build ----------------
__global__ void hist_kernel(const int* __restrict__ dst) {
    int e = blockIdx.x * blockDim.x + threadIdx.x;
    if (e < N_EDGES) atomicAdd(&g_deg[dst[e]], 1);
}

__global__ void scan1_kernel() {
    __shared__ int wsum[8];
    int t = threadIdx.x, b = blockIdx.x;
    int idx = b * 256 + t;
    int lane = t & 31, wid = t >> 5;
    int v = (idx < N_NODES) ? g_deg[idx] : 0;
    int x = v;
#pragma unroll
    for (int o = 1; o < 32; o <<= 1) {
        int y = __shfl_up_sync(0xffffffffu, x, o);
        if (lane >= o) x += y;
    }
    if (lane == 31) wsum[wid] = x;
    __syncthreads();
    if (t == 0) {
        int run = 0;
#pragma unroll
        for (int i = 0; i < 8; i++) { int tmp = wsum[i]; wsum[i] = run; run += tmp; }
        g_blocksum[b] = run;
    }
    __syncthreads();
    int incl = x + wsum[wid];
    if (idx < N_NODES) g_ptr[idx + 1] = incl;
}

__global__ void scan2_kernel() {
    __shared__ int ws[4];
    int t = threadIdx.x;
    int lane = t & 31, w = t >> 5;
    int v = (t < SCAN_NB) ? g_blocksum[t] : 0;
    int x = v;
#pragma unroll
    for (int o = 1; o < 32; o <<= 1) {
        int y = __shfl_up_sync(0xffffffffu, x, o);
        if (lane >= o) x += y;
    }
    if (lane == 31) ws[w] = x;
    __syncthreads();
    if (t == 0) {
        int run = 0;
#pragma unroll
        for (int i = 0; i < 4; i++) { int tmp = ws[i]; ws[i] = run; run += tmp; }
    }
    __syncthreads();
    if (t < SCAN_NB) g_blockoff[t] = x + ws[w] - v;   // exclusive
}

__global__ void scan3_kernel() {
    int t = threadIdx.x, b = blockIdx.x;
    int idx = b * 256 + t;
    if (idx >= N_NODES) return;
    int off = g_blockoff[b];
    int incl = g_ptr[idx + 1] + off;
    g_ptr[idx + 1] = incl;
    g_cursor[idx] = incl - g_deg[idx];
    if (idx == 0) g_ptr[0] = 0;
}

__global__ void scatter_kernel(const int* __restrict__ src,
                               const int* __restrict__ dst) {
    int e = blockIdx.x * blockDim.x + threadIdx.x;
    if (e < N_EDGES) {
        int p = atomicAdd(&g_cursor[dst[e]], 1);
        g_srcs[p] = src[e];
    }
}

// ---------------- GEMM1 (single-term fp16 mma.sync, full-K smem) ------------
#define KS1 136
#define KS1_32 68
#define SMEM_G (2 * 128 * KS1 * 2)   // 69632 bytes: Ah, Bh

__global__ __launch_bounds__(256) void gemm1_mma(const float* __restrict__ feat,
                                                 const float* __restrict__ biasg) {
    extern __shared__ unsigned short sm[];
    unsigned short* Ah = sm;
    unsigned short* Bh = Ah + 128 * KS1;
    const int tid = threadIdx.x;
    const int warp = tid >> 5, lane = tid & 31;
    const int wm = warp >> 2, wn = warp & 3;
    const int g = lane >> 2, t = lane & 3;
    const int row0 = blockIdx.y * 128;
    const int half = blockIdx.x;

    // fill A once: feat fp32 -> fp16
    for (int idx = tid; idx < 4096; idx += 256) {
        int r = idx >> 5, k4 = idx & 31;
        int gr = row0 + r;
        float4 f = make_float4(0.f, 0.f, 0.f, 0.f);
        if (gr < N_NODES) f = *(const float4*)(feat + gr * 128 + k4 * 4);
        *(uint2*)(Ah + r * KS1 + k4 * 4) = make_uint2(f2h2(f.x, f.y), f2h2(f.z, f.w));
    }

    const uint32_t* Ah32 = (const uint32_t*)Ah;
    const uint32_t* Bh32 = (const uint32_t*)Bh;

    for (int i = 0; i < 4; i++) {
        int bx = half * 4 + i;
        for (int idx = tid; idx < 4096; idx += 256) {
            int r = idx >> 5, k4 = idx & 31;
            int n = bx * 128 + r;
            *(uint2*)(Bh + r * KS1 + k4 * 4) = *(const uint2*)(g_WT1h + n * 128 + k4 * 4);
        }
        __syncthreads();

        float c[4][4][4];
#pragma unroll
        for (int a = 0; a < 4; a++)
#pragma unroll
            for (int bq = 0; bq < 4; bq++)
#pragma unroll
                for (int q = 0; q < 4; q++) c[a][bq][q] = 0.f;

#pragma unroll
        for (int ks = 0; ks < 8; ks++) {
            int kb = ks * 8;
            uint32_t ah[4][4], bh[4][2];
#pragma unroll
            for (int rb = 0; rb < 4; rb++) {
                int base = (wm * 64 + rb * 16 + g) * KS1_32 + kb + t;
                ah[rb][0] = Ah32[base];             ah[rb][1] = Ah32[base + 8 * KS1_32];
                ah[rb][2] = Ah32[base + 4];         ah[rb][3] = Ah32[base + 8 * KS1_32 + 4];
            }
#pragma unroll
            for (int nb = 0; nb < 4; nb++) {
                int base = (wn * 32 + nb * 8 + g) * KS1_32 + kb + t;
                bh[nb][0] = Bh32[base];  bh[nb][1] = Bh32[base + 4];
            }
#pragma unroll
            for (int rb = 0; rb < 4; rb++)
#pragma unroll
                for (int nb = 0; nb < 4; nb++)
                    mma_f16(c[rb][nb], ah[rb][0], ah[rb][1], ah[rb][2], ah[rb][3],
                            bh[nb][0], bh[nb][1]);
        }
#pragma unroll
        for (int rb = 0; rb < 4; rb++) {
            int gr0 = row0 + wm * 64 + rb * 16 + g;
#pragma unroll
            for (int nb = 0; nb < 4; nb++) {
                int col = bx * 128 + wn * 32 + nb * 8 + 2 * t;
                float* cc = c[rb][nb];
                if (col < 512) {
                    if (gr0 < N_NODES)
                        *(uint32_t*)(g_h16 + gr0 * HD + col) = f2h2(cc[0], cc[1]);
                    if (gr0 + 8 < N_NODES)
                        *(uint32_t*)(g_h16 + (gr0 + 8) * HD + col) = f2h2(cc[2], cc[3]);
                } else {
                    int cb = col - 512;
                    float2 bv = *(const float2*)(biasg + cb);
                    if (gr0 < N_NODES)
                        *(float2*)(g_rst + gr0 * HD + cb) =
                            make_float2(cc[0] + bv.x, cc[1] + bv.y);
                    if (gr0 + 8 < N_NODES)
                        *(float2*)(g_rst + (gr0 + 8) * HD + cb) =
                            make_float2(cc[2] + bv.x, cc[3] + bv.y);
                }
            }
        }
        __syncthreads();
    }
}

// ---------------- aggregation: 4 nodes per warp, fp16 gather, prefetch ------
__global__ __launch_bounds__(256) void agg_kernel() {
    int wg = blockIdx.x * 8 + (threadIdx.x >> 5);
    int lane = threadIdx.x & 31;
#pragma unroll 1
    for (int q = 0; q < 4; q++) {
        int v = wg * 4 + q;
        if (v >= N_NODES) return;
        int start = g_ptr[v], end = g_ptr[v + 1];
        if (start == end) continue;
        float4 er = *(const float4*)(g_er + v * 4);

        float4 a0 = make_float4(0.f, 0.f, 0.f, 0.f);
        float4 a1 = a0, a2 = a0, a3 = a0;
        float d0 = 0.f, d1 = 0.f, d2 = 0.f, d3 = 0.f;

        int s = g_srcs[start];
        float4 el = *(const float4*)(g_el + s * 4);
        for (int j = start; j < end; j++) {
            int jn = (j + 1 < end) ? j + 1 : j;
            int s2 = g_srcs[jn];
            float4 el2 = *(const float4*)(g_el + s2 * 4);

            const unsigned short* hp = g_h16 + s * HD + lane * 4;
            uint2 q0 = *(const uint2*)(hp);
            uint2 q1 = *(const uint2*)(hp + 128);
            uint2 q2 = *(const uint2*)(hp + 256);
            uint2 q3 = *(const uint2*)(hp + 384);

            float e0 = el.x + er.x; e0 = (e0 > 0.f) ? e0 : NEG_SLOPE * e0;
            float e1 = el.y + er.y; e1 = (e1 > 0.f) ? e1 : NEG_SLOPE * e1;
            float e2 = el.z + er.z; e2 = (e2 > 0.f) ? e2 : NEG_SLOPE * e2;
            float e3 = el.w + er.w; e3 = (e3 > 0.f) ? e3 : NEG_SLOPE * e3;
            float w0 = __expf(e0), w1 = __expf(e1), w2 = __expf(e2), w3 = __expf(e3);
            d0 += w0; d1 += w1; d2 += w2; d3 += w3;

            float2 p;
            p = h2f(q0.x); a0.x += w0 * p.x; a0.y += w0 * p.y;
            p = h2f(q0.y); a0.z += w0 * p.x; a0.w += w0 * p.y;
            p = h2f(q1.x); a1.x += w1 * p.x; a1.y += w1 * p.y;
            p = h2f(q1.y); a1.z += w1 * p.x; a1.w += w1 * p.y;
            p = h2f(q2.x); a2.x += w2 * p.x; a2.y += w2 * p.y;
            p = h2f(q2.y); a2.z += w2 * p.x; a2.w += w2 * p.y;
            p = h2f(q3.x); a3.x += w3 * p.x; a3.y += w3 * p.y;
            p = h2f(q3.y); a3.z += w3 * p.x; a3.w += w3 * p.y;

            s = s2; el = el2;
        }
        float i0 = 1.f / d0, i1 = 1.f / d1, i2 = 1.f / d2, i3 = 1.f / d3;
        float* o = g_rst + v * HD + lane * 4;
        float4 c0 = *(float4*)(o);
        float4 c1 = *(float4*)(o + 128);
        float4 c2 = *(float4*)(o + 256);
        float4 c3 = *(float4*)(o + 384);
        c0.x += a0.x * i0; c0.y += a0.y * i0; c0.z += a0.z * i0; c0.w += a0.w * i0;
        c1.x += a1.x * i1; c1.y += a1.y * i1; c1.z += a1.z * i1; c1.w += a1.w * i1;
        c2.x += a2.x * i2; c2.y += a2.y * i2; c2.z += a2.z * i2; c2.w += a2.w * i2;
        c3.x += a3.x * i3; c3.y += a3.y * i3; c3.z += a3.z * i3; c3.w += a3.w * i3;
        *(float4*)(o)       = c0;
        *(float4*)(o + 128) = c1;
        *(float4*)(o + 256) = c2;
        *(float4*)(o + 384) = c3;
    }
}

// ---------------- BatchNorm stats ----------------
__global__ void bn_part_kernel() {
    int c = threadIdx.x;
    float s = 0.f, q = 0.f;
    for (int r = blockIdx.x; r < N_NODES; r += gridDim.x) {
        float x = g_rst[r * HD + c];
        s += x;
        q += x * x;
    }
    g_psum[blockIdx.x * HD + c] = s;
    g_psq[blockIdx.x * HD + c] = q;
}

__global__ void bn_final_kernel(const float* __restrict__ gamma,
                                const float* __restrict__ beta) {
    int c = threadIdx.x;
    float s = 0.f, q = 0.f;
    for (int b = 0; b < BN_BLOCKS; b++) {
        s += g_psum[b * HD + c];
        q += g_psq[b * HD + c];
    }
    float mu = s / (float)N_NODES;
    float var = q / (float)N_NODES - mu * mu;
    float rstd = rsqrtf(var + BN_EPS);
    float sc = gamma[c] * rstd;
    g_scale[c] = sc;
    g_shift[c] = beta[c] - mu * sc;
}

// ---------------- GEMM2 (single-term fp16 mma.sync, BK=128) ----------------
__global__ __launch_bounds__(256) void gemm2_mma(const float* __restrict__ bout,
                                                 float* __restrict__ out) {
    extern __shared__ unsigned short sm[];
    unsigned short* Ah = sm;
    unsigned short* Bh = Ah + 128 * KS1;
    const int tid = threadIdx.x;
    const int warp = tid >> 5, lane = tid & 31;
    const int wm = warp >> 2, wn = warp & 3;
    const int g = lane >> 2, t = lane & 3;
    const int row0 = blockIdx.x * 128;

    const uint32_t* Ah32 = (const uint32_t*)Ah;
    const uint32_t* Bh32 = (const uint32_t*)Bh;

    float c[4][4][4];
#pragma unroll
    for (int a = 0; a < 4; a++)
#pragma unroll
        for (int bq = 0; bq < 4; bq++)
#pragma unroll
            for (int q = 0; q < 4; q++) c[a][bq][q] = 0.f;

    for (int kc = 0; kc < 4; kc++) {
        int k0 = kc * 128;
        for (int idx = tid; idx < 4096; idx += 256) {
            int r = idx >> 5, k4 = idx & 31;
            int gr = row0 + r;
            int col = k0 + k4 * 4;
            float4 v = make_float4(0.f, 0.f, 0.f, 0.f);
            if (gr < N_NODES) {
                float4 x = *(const float4*)(g_rst + gr * HD + col);
                float4 sc = *(const float4*)(g_scale + col);
                float4 sh = *(const float4*)(g_shift + col);
                v.x = fmaxf(sc.x * x.x + sh.x, 0.f);
                v.y = fmaxf(sc.y * x.y + sh.y, 0.f);
                v.z = fmaxf(sc.z * x.z + sh.z, 0.f);
                v.w = fmaxf(sc.w * x.w + sh.w, 0.f);
            }
            *(uint2*)(Ah + r * KS1 + k4 * 4) = make_uint2(f2h2(v.x, v.y), f2h2(v.z, v.w));
            *(uint2*)(Bh + r * KS1 + k4 * 4) = *(const uint2*)(g_WT2h + r * 512 + col);
        }
        __syncthreads();
#pragma unroll
        for (int ks = 0; ks < 8; ks++) {
            int kb = ks * 8;
            uint32_t ah[4][4], bh[4][2];
#pragma unroll
            for (int rb = 0; rb < 4; rb++) {
                int base = (wm * 64 + rb * 16 + g) * KS1_32 + kb + t;
                ah[rb][0] = Ah32[base];             ah[rb][1] = Ah32[base + 8 * KS1_32];
                ah[rb][2] = Ah32[base + 4];         ah[rb][3] = Ah32[base + 8 * KS1_32 + 4];
            }
#pragma unroll
            for (int nb = 0; nb < 4; nb++) {
                int base = (wn * 32 + nb * 8 + g) * KS1_32 + kb + t;
                bh[nb][0] = Bh32[base];  bh[nb][1] = Bh32[base + 4];
            }
#pragma unroll
            for (int rb = 0; rb < 4; rb++)
#pragma unroll
                for (int nb = 0; nb < 4; nb++)
                    mma_f16(c[rb][nb], ah[rb][0], ah[rb][1], ah[rb][2], ah[rb][3],
                            bh[nb][0], bh[nb][1]);
        }
        __syncthreads();
    }
#pragma unroll
    for (int rb = 0; rb < 4; rb++) {
        int gr0 = row0 + wm * 64 + rb * 16 + g;
#pragma unroll
        for (int nb = 0; nb < 4; nb++) {
            int col = wn * 32 + nb * 8 + 2 * t;
            float* cc = c[rb][nb];
            float2 bv = *(const float2*)(bout + col);
            if (gr0 < N_NODES)
                *(float2*)(out + gr0 * OUTF + col) =
                    make_float2(cc[0] + bv.x, cc[1] + bv.y);
            if (gr0 + 8 < N_NODES)
                *(float2*)(out + (gr0 + 8) * OUTF + col) =
                    make_float2(cc[2] + bv.x, cc[3] + bv.y);
        }
    }
}

// ---------------- launch (fork/join overlap) ----------------
extern "C" void kernel_launch(void* const* d_in, const int* in_sizes, int n_in,
                              void* d_out, int out_size) {
    const float* feat    = (const float*)d_in[0];
    const int*   src     = (const int*)d_in[1];
    const int*   dst     = (const int*)d_in[2];
    const float* Wfc     = (const float*)d_in[3];
    const float* attn_l  = (const float*)d_in[4];
    const float* attn_r  = (const float*)d_in[5];
    const float* Wres    = (const float*)d_in[6];
    const float* biasg   = (const float*)d_in[7];
    const float* gamma   = (const float*)d_in[8];
    const float* beta    = (const float*)d_in[9];
    const float* Wout    = (const float*)d_in[10];
    const float* bout    = (const float*)d_in[11];
    float* out = (float*)d_out;

    static cudaStream_t sB = nullptr;
    static cudaEvent_t evRoot = nullptr, evCsr = nullptr;
    if (sB == nullptr) {
        cudaStreamCreateWithFlags(&sB, cudaStreamNonBlocking);
        cudaEventCreateWithFlags(&evRoot, cudaEventDisableTiming);
        cudaEventCreateWithFlags(&evCsr, cudaEventDisableTiming);
        cudaFuncSetAttribute(gemm1_mma, cudaFuncAttributeMaxDynamicSharedMemorySize, SMEM_G);
        cudaFuncSetAttribute(gemm2_mma, cudaFuncAttributeMaxDynamicSharedMemorySize, SMEM_G);
    }

    // main stream: weights prep (also zeroes g_deg)
    prep_kernel<<<SCAN_NB + 128 + 64 + 8, 256>>>(Wfc, Wres, Wout, attn_l, attn_r);
    cudaEventRecord(evRoot, 0);

    // fork: elr + CSR build on side stream (independent of gemm1)
    cudaStreamWaitEvent(sB, evRoot, 0);
    elr_kernel<<<(N_NODES + 7) / 8, 256, 0, sB>>>(feat);
    hist_kernel<<<(N_EDGES + 255) / 256, 256, 0, sB>>>(dst);
    scan1_kernel<<<SCAN_NB, 256, 0, sB>>>();
    scan2_kernel<<<1, 128, 0, sB>>>();
    scan3_kernel<<<SCAN_NB, 256, 0, sB>>>();
    scatter_kernel<<<(N_EDGES + 255) / 256, 256, 0, sB>>>(src, dst);
    cudaEventRecord(evCsr, sB);

    // main stream: projection GEMM (overlaps elr + CSR chain)
    gemm1_mma<<<dim3(2, NROWB), 256, SMEM_G>>>(feat, biasg);

    // join: aggregation needs both paths
    cudaStreamWaitEvent(0, evCsr, 0);
    agg_kernel<<<(N_NODES + 31) / 32, 256>>>();
    bn_part_kernel<<<BN_BLOCKS, HD>>>();
    bn_final_kernel<<<1, HD>>>(gamma, beta);
    gemm2_mma<<<NROWB, 256, SMEM_G>>>(bout, out);
}